// round 4
// baseline (speedup 1.0000x reference)
#include <cuda_runtime.h>
#include <math.h>

#define NB    8
#define NCC   16384
#define HIDD  128
#define OUTD  64
#define LDA_H 132
#define LDA_O 68
#define WLD   136

#define OFF_T1  8448
#define OFF_O   16896
#define OFF_WT  21248
#define OFF_TEN 25600
#define OFF_AUX 25664
#define SMEM_FLOATS 25696
#define SMEM_BYTES  (SMEM_FLOATS * 4)

typedef unsigned long long u64;

// ---------------- f32x2 packed helpers ----------------
__device__ __forceinline__ void ffma2(u64& d, u64 a, u64 b) {
    asm("fma.rn.f32x2 %0, %1, %2, %0;" : "+l"(d) : "l"(a), "l"(b));
}
__device__ __forceinline__ u64 pack2(float x, float y) {
    u64 r; asm("mov.b64 %0, {%1, %2};" : "=l"(r) : "f"(x), "f"(y)); return r;
}
__device__ __forceinline__ float2 unpack2(u64 v) {
    float2 r; asm("mov.b64 {%0, %1}, %2;" : "=f"(r.x), "=f"(r.y) : "l"(v)); return r;
}

// ---------------- device scratch (no allocation allowed) ----------------
__device__ float g_ea1b[NB * 128];
__device__ float g_eg1b[NB * 128];
__device__ float g_aabs[NB];
__device__ float g_fsum[NB * 8 * HIDD];
__device__ float g_dsum[NB * 8 * HIDD];
__device__ float g_fm[NB * 8 * HIDD];
__device__ float g_m0[NB * HIDD];
__device__ float g_interf[HIDD];
__device__ float g_numer[OUTD];
__device__ float g_denom, g_tsum;

// ---------------- Stage A: per-branch folded biases + zeroing ----------------
__global__ void __launch_bounds__(256) stageA(
    const float* __restrict__ x, const float* __restrict__ noise,
    const float* __restrict__ amps,
    const float* __restrict__ eaW1, const float* __restrict__ eaB1,
    const float* __restrict__ egW1, const float* __restrict__ egB1)
{
    __shared__ float sXB[NB * 64];
    int tid = threadIdx.x;
    for (int i = tid; i < NB * 8 * HIDD; i += 256) { g_fsum[i] = 0.f; g_dsum[i] = 0.f; }
    if (tid < OUTD) g_numer[tid] = 0.f;
    if (tid == 0) {
        g_denom = 0.f; g_tsum = 0.f;
        float s = 1e-8f, t[NB];
        for (int b = 0; b < NB; b++) { t[b] = fabsf(amps[b]); s += t[b]; }
        for (int b = 0; b < NB; b++) g_aabs[b] = t[b] / s;
    }
    for (int i = tid; i < NB * 64; i += 256) {
        int b = i >> 6, k = i & 63;
        sXB[i] = x[k] + noise[i] * 0.05f * (float)(b + 1);
    }
    __syncthreads();
    for (int i = tid; i < NB * 128; i += 256) {
        int b = i >> 7, j = i & 127;
        float s1 = eaB1[j], s2 = egB1[j];
        const float* xb = sXB + b * 64;
        #pragma unroll 8
        for (int k = 0; k < 64; k++) {
            s1 = fmaf(xb[k], eaW1[j * 192 + k], s1);
            s2 = fmaf(xb[k], egW1[j * 192 + k], s2);
        }
        g_ea1b[i] = s1; g_eg1b[i] = s2;
    }
}

// ---------------- packed GEMM tile helper ----------------
// acc[i][q] holds output cols (cg*4 + 2q, cg*4 + 2q + 1) as packed f32x2.
__device__ __forceinline__ void gemm_tile(
    u64 (&acc)[8][2], const float* __restrict__ sA, int lda,
    const float* __restrict__ W, int ldw, int row0, int colOff,
    int K, int N, float* sWT, int tid, int r0, int cg)
{
    for (int kt = 0; kt < K; kt += 32) {
        __syncthreads();
        for (int idx = tid; idx < N * 32; idx += 256) {
            int j = idx >> 5, kk = idx & 31;
            sWT[kk * WLD + j] = W[(row0 + j) * ldw + colOff + kt + kk];
        }
        __syncthreads();
        if (cg * 4 < N) {
            #pragma unroll 2
            for (int kk = 0; kk < 32; kk += 4) {
                ulonglong2 w0 = *(const ulonglong2*)(sWT + (kk + 0) * WLD + cg * 4);
                ulonglong2 w1 = *(const ulonglong2*)(sWT + (kk + 1) * WLD + cg * 4);
                ulonglong2 w2 = *(const ulonglong2*)(sWT + (kk + 2) * WLD + cg * 4);
                ulonglong2 w3 = *(const ulonglong2*)(sWT + (kk + 3) * WLD + cg * 4);
                #pragma unroll
                for (int i = 0; i < 8; i++) {
                    float4 a = *(const float4*)(sA + (r0 + i) * lda + kt + kk);
                    u64 ax = pack2(a.x, a.x), ay = pack2(a.y, a.y);
                    u64 az = pack2(a.z, a.z), aw = pack2(a.w, a.w);
                    ffma2(acc[i][0], ax, w0.x); ffma2(acc[i][1], ax, w0.y);
                    ffma2(acc[i][0], ay, w1.x); ffma2(acc[i][1], ay, w1.y);
                    ffma2(acc[i][0], az, w2.x); ffma2(acc[i][1], az, w2.y);
                    ffma2(acc[i][0], aw, w3.x); ffma2(acc[i][1], aw, w3.y);
                }
            }
        }
    }
}

// ---------------- Stage B: fused per-cell pipeline ----------------
__global__ void __launch_bounds__(256, 1) stageB(
    const float* __restrict__ hiddens,
    const float* __restrict__ eaW1, const float* __restrict__ eaW2, const float* __restrict__ eaB2,
    const float* __restrict__ egW1, const float* __restrict__ egW2, const float* __restrict__ egB2,
    const float* __restrict__ Wih,  const float* __restrict__ Whh,
    const float* __restrict__ bih,  const float* __restrict__ bhh,
    float* __restrict__ out, long long nh_off)
{
    extern __shared__ float sm[];
    float* sH   = sm;
    float* sT1  = sm + OFF_T1;
    float* sO   = sm + OFF_O;
    float* sWT  = sm + OFF_WT;
    float* sTen = sm + OFF_TEN;
    float* sAux = sm + OFF_AUX;

    const int tid = threadIdx.x;
    const int rg = tid >> 5, cg = tid & 31, r0 = rg * 8;
    const int c0 = blockIdx.x * 8;
    const int b = rg;

    if (tid < 8) sAux[16 + tid] = g_aabs[tid];
    for (int idx = tid; idx < 64 * 128; idx += 256) {
        int r = idx >> 7, k = idx & 127;
        sH[r * LDA_H + k] = hiddens[((long long)((r >> 3) * NCC + c0 + (r & 7))) * HIDD + k];
    }

    u64 acc[8][2];

    // t1a = relu(biasA + H @ eaW1h^T)
    {
        u64 b01 = pack2(g_ea1b[b * 128 + cg * 4],     g_ea1b[b * 128 + cg * 4 + 1]);
        u64 b23 = pack2(g_ea1b[b * 128 + cg * 4 + 2], g_ea1b[b * 128 + cg * 4 + 3]);
        #pragma unroll
        for (int i = 0; i < 8; i++) { acc[i][0] = b01; acc[i][1] = b23; }
    }
    gemm_tile(acc, sH, LDA_H, eaW1, 192, 0, 64, 128, 128, sWT, tid, r0, cg);
    #pragma unroll
    for (int i = 0; i < 8; i++) {
        float2 p0 = unpack2(acc[i][0]), p1 = unpack2(acc[i][1]);
        *(float4*)(sT1 + (r0 + i) * LDA_H + cg * 4) =
            make_float4(fmaxf(p0.x, 0.f), fmaxf(p0.y, 0.f), fmaxf(p1.x, 0.f), fmaxf(p1.y, 0.f));
    }

    // a = t1a @ eaW2^T + eaB2
    {
        u64 b01 = 0, b23 = 0;
        if (cg < 16) {
            b01 = pack2(eaB2[cg * 4],     eaB2[cg * 4 + 1]);
            b23 = pack2(eaB2[cg * 4 + 2], eaB2[cg * 4 + 3]);
        }
        #pragma unroll
        for (int i = 0; i < 8; i++) { acc[i][0] = b01; acc[i][1] = b23; }
    }
    gemm_tile(acc, sT1, LDA_H, eaW2, 128, 0, 0, 128, 64, sWT, tid, r0, cg);
    if (cg < 16) {
        #pragma unroll
        for (int i = 0; i < 8; i++) {
            float2 p0 = unpack2(acc[i][0]), p1 = unpack2(acc[i][1]);
            *(float4*)(sO + (r0 + i) * LDA_O + cg * 4) = make_float4(p0.x, p0.y, p1.x, p1.y);
        }
    }

    // t1g
    {
        u64 b01 = pack2(g_eg1b[b * 128 + cg * 4],     g_eg1b[b * 128 + cg * 4 + 1]);
        u64 b23 = pack2(g_eg1b[b * 128 + cg * 4 + 2], g_eg1b[b * 128 + cg * 4 + 3]);
        #pragma unroll
        for (int i = 0; i < 8; i++) { acc[i][0] = b01; acc[i][1] = b23; }
    }
    gemm_tile(acc, sH, LDA_H, egW1, 192, 0, 64, 128, 128, sWT, tid, r0, cg);
    #pragma unroll
    for (int i = 0; i < 8; i++) {
        float2 p0 = unpack2(acc[i][0]), p1 = unpack2(acc[i][1]);
        *(float4*)(sT1 + (r0 + i) * LDA_H + cg * 4) =
            make_float4(fmaxf(p0.x, 0.f), fmaxf(p0.y, 0.f), fmaxf(p1.x, 0.f), fmaxf(p1.y, 0.f));
    }

    // g ; out = a - g
    {
        u64 b01 = 0, b23 = 0;
        if (cg < 16) {
            b01 = pack2(egB2[cg * 4],     egB2[cg * 4 + 1]);
            b23 = pack2(egB2[cg * 4 + 2], egB2[cg * 4 + 3]);
        }
        #pragma unroll
        for (int i = 0; i < 8; i++) { acc[i][0] = b01; acc[i][1] = b23; }
    }
    gemm_tile(acc, sT1, LDA_H, egW2, 128, 0, 0, 128, 64, sWT, tid, r0, cg);
    if (cg < 16) {
        #pragma unroll
        for (int i = 0; i < 8; i++) {
            float2 p0 = unpack2(acc[i][0]), p1 = unpack2(acc[i][1]);
            float4* p = (float4*)(sO + (r0 + i) * LDA_O + cg * 4);
            float4 v = *p;
            v.x -= p0.x; v.y -= p0.y; v.z -= p1.x; v.w -= p1.y;
            *p = v;
        }
    }
    __syncthreads();

    // tension
    if (tid < 64) {
        float s = 0.f;
        #pragma unroll 16
        for (int o = 0; o < 64; o++) { float v = sO[tid * LDA_O + o]; s = fmaf(v, v, s); }
        sTen[tid] = s * (1.f / 64.f);
    }
    __syncthreads();
    if (tid < 8) {
        float s = 0.f;
        #pragma unroll
        for (int bb = 0; bb < 8; bb++) s += sTen[bb * 8 + tid];
        float avg = s * 0.125f;
        sAux[tid] = avg; sAux[8 + tid] = expf(avg);
    }
    __syncthreads();
    if (tid < 64) {
        float v = 0.f;
        for (int ci = 0; ci < 8; ci++) {
            float co = 0.f;
            #pragma unroll
            for (int bb = 0; bb < 8; bb++)
                co = fmaf(sAux[16 + bb], sO[(bb * 8 + ci) * LDA_O + tid], co);
            v = fmaf(sAux[8 + ci], co, v);
        }
        atomicAdd(&g_numer[tid], v);
    } else if (tid == 64) {
        float se = 0.f, st = 0.f;
        for (int ci = 0; ci < 8; ci++) { se += sAux[8 + ci]; st += sAux[ci]; }
        atomicAdd(&g_denom, se); atomicAdd(&g_tsum, st);
    }

    // ---- GRU ----
    // r gate -> parked in sT1 (thread-exclusive slots)
    #pragma unroll
    for (int q = 0; q < 2; q++) {
        int u0 = cg * 4 + 2 * q, u1 = u0 + 1;
        u64 base = pack2(bih[u0] + bhh[u0], bih[u1] + bhh[u1]);
        u64 wt   = pack2(Wih[u0 * 65 + 64], Wih[u1 * 65 + 64]);
        #pragma unroll
        for (int i = 0; i < 8; i++) {
            acc[i][q] = base;
            ffma2(acc[i][q], pack2(sTen[r0 + i], sTen[r0 + i]), wt);
        }
    }
    gemm_tile(acc, sO, LDA_O, Wih, 65, 0, 0, 64, 128, sWT, tid, r0, cg);
    gemm_tile(acc, sH, LDA_H, Whh, 128, 0, 0, 128, 128, sWT, tid, r0, cg);
    #pragma unroll
    for (int i = 0; i < 8; i++) {
        float2 p0 = unpack2(acc[i][0]), p1 = unpack2(acc[i][1]);
        sT1[(r0 + i) * LDA_H + cg * 4 + 0] = 1.f / (1.f + expf(-p0.x));
        sT1[(r0 + i) * LDA_H + cg * 4 + 1] = 1.f / (1.f + expf(-p0.y));
        sT1[(r0 + i) * LDA_H + cg * 4 + 2] = 1.f / (1.f + expf(-p1.x));
        sT1[(r0 + i) * LDA_H + cg * 4 + 3] = 1.f / (1.f + expf(-p1.y));
    }

    // z gate (registers)
    float zReg[8][4];
    #pragma unroll
    for (int q = 0; q < 2; q++) {
        int u0 = 128 + cg * 4 + 2 * q, u1 = u0 + 1;
        u64 base = pack2(bih[u0] + bhh[u0], bih[u1] + bhh[u1]);
        u64 wt   = pack2(Wih[u0 * 65 + 64], Wih[u1 * 65 + 64]);
        #pragma unroll
        for (int i = 0; i < 8; i++) {
            acc[i][q] = base;
            ffma2(acc[i][q], pack2(sTen[r0 + i], sTen[r0 + i]), wt);
        }
    }
    gemm_tile(acc, sO, LDA_O, Wih, 65, 128, 0, 64, 128, sWT, tid, r0, cg);
    gemm_tile(acc, sH, LDA_H, Whh, 128, 128, 0, 128, 128, sWT, tid, r0, cg);
    #pragma unroll
    for (int i = 0; i < 8; i++) {
        float2 p0 = unpack2(acc[i][0]), p1 = unpack2(acc[i][1]);
        zReg[i][0] = 1.f / (1.f + expf(-p0.x));
        zReg[i][1] = 1.f / (1.f + expf(-p0.y));
        zReg[i][2] = 1.f / (1.f + expf(-p1.x));
        zReg[i][3] = 1.f / (1.f + expf(-p1.y));
    }

    // n gate: inn (acc) and hn (accH) kept separate
    u64 accH[8][2];
    #pragma unroll
    for (int q = 0; q < 2; q++) {
        int u0 = 256 + cg * 4 + 2 * q, u1 = u0 + 1;
        u64 bi = pack2(bih[u0], bih[u1]);
        u64 bh = pack2(bhh[u0], bhh[u1]);
        u64 wt = pack2(Wih[u0 * 65 + 64], Wih[u1 * 65 + 64]);
        #pragma unroll
        for (int i = 0; i < 8; i++) {
            acc[i][q] = bi;
            ffma2(acc[i][q], pack2(sTen[r0 + i], sTen[r0 + i]), wt);
            accH[i][q] = bh;
        }
    }
    gemm_tile(acc,  sO, LDA_O, Wih, 65, 256, 0, 64, 128, sWT, tid, r0, cg);
    gemm_tile(accH, sH, LDA_H, Whh, 128, 256, 0, 128, 128, sWT, tid, r0, cg);

    // combine -> newh v0 into sT1, faction sums via atomics
    const int f = c0 >> 11;
    const bool deb = (c0 & 2047) < 512;
    float fs[4] = {0.f, 0.f, 0.f, 0.f};
    #pragma unroll
    for (int i = 0; i < 8; i++) {
        int r = r0 + i;
        float4 hv = *(const float4*)(sH + r * LDA_H + cg * 4);
        float h[4] = {hv.x, hv.y, hv.z, hv.w};
        float2 i0 = unpack2(acc[i][0]), i1 = unpack2(acc[i][1]);
        float2 h0 = unpack2(accH[i][0]), h1 = unpack2(accH[i][1]);
        float inn[4] = {i0.x, i0.y, i1.x, i1.y};
        float hn[4]  = {h0.x, h0.y, h1.x, h1.y};
        #pragma unroll
        for (int j = 0; j < 4; j++) {
            float rr = sT1[r * LDA_H + cg * 4 + j];
            float n = tanhf(inn[j] + rr * hn[j]);
            float zz = zReg[i][j];
            float v = (1.f - zz) * n + zz * h[j];
            sT1[r * LDA_H + cg * 4 + j] = v;
            fs[j] += v;
        }
    }
    #pragma unroll
    for (int j = 0; j < 4; j++) {
        int u = cg * 4 + j;
        atomicAdd(&g_fsum[(b * 8 + f) * HIDD + u], fs[j]);
        if (deb) atomicAdd(&g_dsum[(b * 8 + f) * HIDD + u], fs[j]);
    }
    __syncthreads();

    // coalesced copy-out of v0
    for (int idx = tid; idx < 64 * 128; idx += 256) {
        int r = idx >> 7, k = idx & 127;
        out[nh_off + ((long long)((r >> 3) * NCC + c0 + (r & 7))) * HIDD + k] = sT1[r * LDA_H + k];
    }
}

// ---------------- Stage C: means, interf, pred, scalar ----------------
__global__ void __launch_bounds__(256) stageC(
    const float* __restrict__ mixW, const float* __restrict__ mixb,
    const float* __restrict__ headW, const float* __restrict__ headb,
    const int* __restrict__ stepp, float* __restrict__ out, long long nh_off)
{
    __shared__ float sMF[NB * HIDD];
    __shared__ float sC[OUTD];
    int tid = threadIdx.x;
    int st = *stepp;
    for (int i = tid; i < NB * HIDD; i += 256) {
        int b = i >> 7, u = i & 127;
        float Sf = 0.f, Sd = 0.f;
        for (int f = 0; f < 8; f++) {
            float fsv = g_fsum[(b * 8 + f) * HIDD + u];
            float fm  = fsv * (1.f / 2048.f);
            g_fm[(b * 8 + f) * HIDD + u] = fm;
            Sf += fsv;
            Sd += 0.85f * g_dsum[(b * 8 + f) * HIDD + u] + 76.8f * fm;
        }
        float m0 = Sf * (1.f / 16384.f);
        g_m0[i] = m0;
        sMF[i] = (st > 5) ? (m0 + 0.15f * (0.25f * m0 - Sd * (1.f / 16384.f))) : m0;
    }
    __syncthreads();
    if (tid < HIDD) {
        float v = mixb[tid];
        #pragma unroll 16
        for (int t = 0; t < NB * HIDD; t++) v = fmaf(sMF[t], mixW[tid * (NB * HIDD) + t], v);
        g_interf[tid] = v;
    }
    if (tid >= 128 && tid < 192) sC[tid - 128] = g_numer[tid - 128] / g_denom;
    __syncthreads();
    if (tid < OUTD) {
        float p = headb[tid];
        #pragma unroll
        for (int o = 0; o < OUTD; o++) p = fmaf(sC[o], headW[tid * OUTD + o], p);
        out[tid] = p;
    } else if (tid == 64) {
        out[nh_off - 1] = g_tsum * (1.f / 16384.f);
    }
}

// ---------------- Stage D: elementwise sync/debate/interf ----------------
__global__ void __launch_bounds__(256) stageD(const int* __restrict__ stepp,
                                              float* __restrict__ out, long long nh_off)
{
    long long idx = (long long)blockIdx.x * 256 + threadIdx.x;
    int u = (int)(idx & 127);
    long long rc = idx >> 7;
    int c = (int)(rc & (NCC - 1));
    int b = (int)(rc >> 14);
    float v0 = out[nh_off + idx];
    int f = c >> 11;
    float v = 0.85f * v0 + 0.15f * g_fm[(b * 8 + f) * HIDD + u];
    if (*stepp > 5 && (c & 2047) < 512) v = 0.85f * v + 0.15f * g_m0[b * HIDD + u];
    if (b == 0) v += 0.05f * g_interf[u];
    out[nh_off + idx] = v;
}

extern "C" void kernel_launch(void* const* d_in, const int* in_sizes, int n_in,
                              void* d_out, int out_size) {
    const float* x     = (const float*)d_in[0];
    const float* noise = (const float*)d_in[1];
    const float* amps  = (const float*)d_in[2];
    const float* hidd  = (const float*)d_in[3];
    const float* eaW1  = (const float*)d_in[4];
    const float* eaB1  = (const float*)d_in[5];
    const float* eaW2  = (const float*)d_in[6];
    const float* eaB2  = (const float*)d_in[7];
    const float* egW1  = (const float*)d_in[8];
    const float* egB1  = (const float*)d_in[9];
    const float* egW2  = (const float*)d_in[10];
    const float* egB2  = (const float*)d_in[11];
    const float* Wih   = (const float*)d_in[12];
    const float* Whh   = (const float*)d_in[13];
    const float* bih   = (const float*)d_in[14];
    const float* bhh   = (const float*)d_in[15];
    const float* headW = (const float*)d_in[16];
    const float* headb = (const float*)d_in[17];
    const float* mixW  = (const float*)d_in[18];
    const float* mixb  = (const float*)d_in[19];
    const int*   step  = (const int*)d_in[20];
    float* out = (float*)d_out;
    long long nh_off = (long long)out_size - (long long)NB * NCC * HIDD;

    cudaFuncSetAttribute(stageB, cudaFuncAttributeMaxDynamicSharedMemorySize, SMEM_BYTES);

    stageA<<<1, 256>>>(x, noise, amps, eaW1, eaB1, egW1, egB1);
    stageB<<<NCC / 8, 256, SMEM_BYTES>>>(hidd, eaW1, eaW2, eaB2, egW1, egW2, egB2,
                                         Wih, Whh, bih, bhh, out, nh_off);
    stageC<<<1, 256>>>(mixW, mixb, headW, headb, step, out, nh_off);
    stageD<<<(NB * NCC * HIDD) / 256, 256>>>(step, out, nh_off);
}

// round 9
// speedup vs baseline: 1.1289x; 1.1289x over previous
#include <cuda_runtime.h>
#include <cuda_bf16.h>
#include <math.h>
#include <stdint.h>

#define NB 8
#define NCC 16384
#define HIDD 128
#define OUTD 64

typedef unsigned int uint32;

// ---- smem byte offsets (stage B) ----
#define SM_TEN 0
#define SM_AVG 256
#define SM_EXP 288
#define SM_AABS 320
#define AHHI 1024
#define AT1HI 34816
#define AOHI 68608
#define SOF 86016
#define SWB 103424
#define SMEM_B_BYTES 169984
// uint offsets of lo blocks relative to hi base
#define A_LO 4224      // 64*66
#define AO_LO 2176     // 64*34

// ---------------- device scratch ----------------
__device__ float g_ea1b[NB*128];
__device__ float g_eg1b[NB*128];
__device__ float g_aabs[NB];
__device__ float g_fsum[NB*8*HIDD];
__device__ float g_dsum[NB*8*HIDD];
__device__ float g_fm[NB*8*HIDD];
__device__ float g_m0[NB*HIDD];
__device__ float g_interf[HIDD];
__device__ float g_numer[OUTD];
__device__ float g_denom, g_tsum;

// pre-packed bf16-pair weight images: hi block then lo block
__device__ __align__(16) uint32 g_Iea1[16384];   // [128][64]u x2
__device__ __align__(16) uint32 g_Ieg1[16384];
__device__ __align__(16) uint32 g_Iea2[8192];    // [64][64]u x2
__device__ __align__(16) uint32 g_Ieg2[8192];    // negated
__device__ __align__(16) uint32 g_Iwih[3][8192]; // [128][32]u x2
__device__ __align__(16) uint32 g_Iwhh[3][16384];// [128][64]u x2

__device__ __forceinline__ void splitPack(float v0, float v1, uint32& hi, uint32& lo) {
    __nv_bfloat16 h0 = __float2bfloat16_rn(v0), h1 = __float2bfloat16_rn(v1);
    hi = (uint32)__bfloat16_as_ushort(h0) | ((uint32)__bfloat16_as_ushort(h1) << 16);
    __nv_bfloat16 l0 = __float2bfloat16_rn(v0 - __bfloat162float(h0));
    __nv_bfloat16 l1 = __float2bfloat16_rn(v1 - __bfloat162float(h1));
    lo = (uint32)__bfloat16_as_ushort(l0) | ((uint32)__bfloat16_as_ushort(l1) << 16);
}
__device__ __forceinline__ float2 unpackBf(uint32 hi, uint32 lo) {
    float a = __bfloat162float(__ushort_as_bfloat16((unsigned short)(hi & 0xFFFF)))
            + __bfloat162float(__ushort_as_bfloat16((unsigned short)(lo & 0xFFFF)));
    float b = __bfloat162float(__ushort_as_bfloat16((unsigned short)(hi >> 16)))
            + __bfloat162float(__ushort_as_bfloat16((unsigned short)(lo >> 16)));
    return make_float2(a, b);
}

__device__ __forceinline__ void mma_bf16(float* c, const uint32* a, uint32 b0, uint32 b1) {
    asm volatile("mma.sync.aligned.m16n8k16.row.col.f32.bf16.bf16.f32 "
        "{%0,%1,%2,%3}, {%4,%5,%6,%7}, {%8,%9}, {%0,%1,%2,%3};"
        : "+f"(c[0]), "+f"(c[1]), "+f"(c[2]), "+f"(c[3])
        : "r"(a[0]), "r"(a[1]), "r"(a[2]), "r"(a[3]), "r"(b0), "r"(b1));
}

// 3-pass split-bf16 warp GEMM. acc[nT][4] fp32. A,W pair-packed [row][k2].
__device__ __forceinline__ void wgemm(float (*acc)[4], int nT,
    const uint32* A, int sa, int aLo, const uint32* W, int sw, int wLo,
    int k2, int r0, int g, int t, int nbase)
{
    for (int kk = 0; kk < k2; kk += 8) {
        const uint32* p0 = A + (r0 + g) * sa + kk;
        const uint32* p1 = A + (r0 + 8 + g) * sa + kk;
        uint32 ah[4] = { p0[t], p1[t], p0[t+4], p1[t+4] };
        uint32 al[4] = { p0[aLo+t], p1[aLo+t], p0[aLo+t+4], p1[aLo+t+4] };
        for (int nt = 0; nt < nT; nt++) {
            const uint32* wr = W + (nbase + nt*8 + g) * sw + kk;
            uint32 b0 = wr[t], b1 = wr[t+4];
            uint32 l0 = wr[wLo+t], l1 = wr[wLo+t+4];
            mma_bf16(acc[nt], ah, b0, b1);
            mma_bf16(acc[nt], al, b0, b1);
            mma_bf16(acc[nt], ah, l0, l1);
        }
    }
}

// ---------------- Stage A ----------------
__global__ void __launch_bounds__(256) stageA(
    const float* __restrict__ x, const float* __restrict__ noise,
    const float* __restrict__ amps,
    const float* __restrict__ eaW1, const float* __restrict__ eaB1,
    const float* __restrict__ egW1, const float* __restrict__ egB1)
{
    __shared__ float sXB[NB*64];
    int tid = threadIdx.x;
    for (int i = tid; i < NB*8*HIDD; i += 256) { g_fsum[i] = 0.f; g_dsum[i] = 0.f; }
    if (tid < OUTD) g_numer[tid] = 0.f;
    if (tid == 0) {
        g_denom = 0.f; g_tsum = 0.f;
        float s = 1e-8f, t[NB];
        for (int b = 0; b < NB; b++) { t[b] = fabsf(amps[b]); s += t[b]; }
        for (int b = 0; b < NB; b++) g_aabs[b] = t[b] / s;
    }
    for (int i = tid; i < NB*64; i += 256) {
        int b = i >> 6, k = i & 63;
        sXB[i] = x[k] + noise[i] * 0.05f * (float)(b + 1);
    }
    __syncthreads();
    for (int i = tid; i < NB*128; i += 256) {
        int b = i >> 7, j = i & 127;
        float s1 = eaB1[j], s2 = egB1[j];
        const float* xb = sXB + b*64;
        #pragma unroll 8
        for (int k = 0; k < 64; k++) {
            s1 = fmaf(xb[k], eaW1[j*192 + k], s1);
            s2 = fmaf(xb[k], egW1[j*192 + k], s2);
        }
        g_ea1b[i] = s1; g_eg1b[i] = s2;
    }
}

// ---------------- Stage A2: pair-packed split weight images ----------------
__global__ void __launch_bounds__(256) stageA2(
    const float* __restrict__ eaW1, const float* __restrict__ egW1,
    const float* __restrict__ eaW2, const float* __restrict__ egW2,
    const float* __restrict__ Wih,  const float* __restrict__ Whh)
{
    int gt = blockIdx.x*256 + threadIdx.x, gs = gridDim.x*256;
    uint32 hi, lo;
    for (int i = gt; i < 8192; i += gs) {            // ea1/eg1: [128][64]u
        int r = i >> 6, cu = i & 63, k = 2*cu;
        splitPack(eaW1[r*192 + 64 + k], eaW1[r*192 + 64 + k + 1], hi, lo);
        g_Iea1[i] = hi; g_Iea1[8192 + i] = lo;
        splitPack(egW1[r*192 + 64 + k], egW1[r*192 + 64 + k + 1], hi, lo);
        g_Ieg1[i] = hi; g_Ieg1[8192 + i] = lo;
    }
    for (int i = gt; i < 4096; i += gs) {            // ea2/eg2: [64][64]u
        int r = i >> 6, cu = i & 63, k = 2*cu;
        splitPack(eaW2[r*128 + k], eaW2[r*128 + k + 1], hi, lo);
        g_Iea2[i] = hi; g_Iea2[4096 + i] = lo;
        splitPack(-egW2[r*128 + k], -egW2[r*128 + k + 1], hi, lo);
        g_Ieg2[i] = hi; g_Ieg2[4096 + i] = lo;
    }
    for (int gg = 0; gg < 3; gg++) {
        for (int i = gt; i < 4096; i += gs) {        // wih: [128][32]u
            int r = i >> 5, cu = i & 31, k = 2*cu;
            splitPack(Wih[(gg*128 + r)*65 + k], Wih[(gg*128 + r)*65 + k + 1], hi, lo);
            g_Iwih[gg][i] = hi; g_Iwih[gg][4096 + i] = lo;
        }
        for (int i = gt; i < 8192; i += gs) {        // whh: [128][64]u
            int r = i >> 6, cu = i & 63, k = 2*cu;
            splitPack(Whh[(gg*128 + r)*128 + k], Whh[(gg*128 + r)*128 + k + 1], hi, lo);
            g_Iwhh[gg][i] = hi; g_Iwhh[gg][8192 + i] = lo;
        }
    }
}

// ---------------- Stage B ----------------
__global__ void __launch_bounds__(256, 1) stageB(
    const float* __restrict__ hiddens, const float* __restrict__ Wih,
    const float* __restrict__ bih, const float* __restrict__ bhh,
    const float* __restrict__ eaB2, const float* __restrict__ egB2,
    float* __restrict__ out, long long nh_off)
{
    extern __shared__ char smem[];
    const int tid = threadIdx.x, wid = tid >> 5, lid = tid & 31;
    const int g = lid >> 2, t = lid & 3;
    const int rt = wid & 3, chalf = wid >> 2, r0 = rt * 16;
    const int c0 = blockIdx.x * 8;

    float* sTen = (float*)(smem + SM_TEN);
    float* sAvg = (float*)(smem + SM_AVG);
    float* sExp = (float*)(smem + SM_EXP);
    float* sAabs = (float*)(smem + SM_AABS);
    uint32* AH  = (uint32*)(smem + AHHI);
    uint32* AT1 = (uint32*)(smem + AT1HI);
    uint32* AO  = (uint32*)(smem + AOHI);
    float*  sOf = (float*)(smem + SOF);
    uint32* SW  = (uint32*)(smem + SWB);
    float*  sRN = (float*)(smem + AT1HI);   // reuse after phase 4
    float*  sNew = (float*)(smem + SWB);    // reuse after last GEMM

    if (tid < 8) sAabs[tid] = g_aabs[tid];

    // build AH pair tiles
    for (int i = tid; i < 64*64; i += 256) {
        int r = i >> 6, cu = i & 63, k = 2*cu;
        const float* hp = hiddens + ((long long)((r >> 3)*NCC + c0 + (r & 7)))*HIDD + k;
        uint32 hi, lo; splitPack(hp[0], hp[1], hi, lo);
        AH[r*66 + cu] = hi; AH[A_LO + r*66 + cu] = lo;
    }

#define CPW(src, n, lgc, swst, wlo) { \
    for (int _i = tid; _i < (n); _i += 256) { \
        int _r = _i >> (lgc), _c = _i & (((1 << (lgc)) - 1)); \
        SW[_r*(swst) + _c] = (src)[_i]; \
        SW[(wlo) + _r*(swst) + _c] = (src)[(n) + _i]; \
    } }

    float acc8[8][4];
    float acc4[4][4];

    // ---- Phase 1: t1a ----
    __syncthreads(); CPW(g_Iea1, 8192, 6, 65, 8320); __syncthreads();
    #pragma unroll
    for (int n = 0; n < 8; n++) { acc8[n][0]=0;acc8[n][1]=0;acc8[n][2]=0;acc8[n][3]=0; }
    wgemm(acc8, 8, AH, 66, A_LO, SW, 65, 8320, 64, r0, g, t, chalf*64);
    #pragma unroll
    for (int n = 0; n < 8; n++) {
        int col = chalf*64 + n*8 + 2*t;
        int rA = r0 + g, rB = rA + 8;
        float v0 = fmaxf(acc8[n][0] + g_ea1b[(rA >> 3)*128 + col], 0.f);
        float v1 = fmaxf(acc8[n][1] + g_ea1b[(rA >> 3)*128 + col + 1], 0.f);
        float v2 = fmaxf(acc8[n][2] + g_ea1b[(rB >> 3)*128 + col], 0.f);
        float v3 = fmaxf(acc8[n][3] + g_ea1b[(rB >> 3)*128 + col + 1], 0.f);
        uint32 hi, lo;
        splitPack(v0, v1, hi, lo); AT1[rA*66 + col/2] = hi; AT1[A_LO + rA*66 + col/2] = lo;
        splitPack(v2, v3, hi, lo); AT1[rB*66 + col/2] = hi; AT1[A_LO + rB*66 + col/2] = lo;
    }

    // ---- Phase 2: a = t1a @ ea2^T + eaB2 ----
    __syncthreads(); CPW(g_Iea2, 4096, 6, 65, 4160); __syncthreads();
    #pragma unroll
    for (int n = 0; n < 4; n++) { acc4[n][0]=0;acc4[n][1]=0;acc4[n][2]=0;acc4[n][3]=0; }
    wgemm(acc4, 4, AT1, 66, A_LO, SW, 65, 4160, 64, r0, g, t, chalf*32);
    #pragma unroll
    for (int n = 0; n < 4; n++) {
        int col = chalf*32 + n*8 + 2*t;
        int rA = r0 + g, rB = rA + 8;
        sOf[rA*68 + col]     = acc4[n][0] + eaB2[col];
        sOf[rA*68 + col + 1] = acc4[n][1] + eaB2[col + 1];
        sOf[rB*68 + col]     = acc4[n][2] + eaB2[col];
        sOf[rB*68 + col + 1] = acc4[n][3] + eaB2[col + 1];
    }

    // ---- Phase 3: t1g ----
    __syncthreads(); CPW(g_Ieg1, 8192, 6, 65, 8320); __syncthreads();
    #pragma unroll
    for (int n = 0; n < 8; n++) { acc8[n][0]=0;acc8[n][1]=0;acc8[n][2]=0;acc8[n][3]=0; }
    wgemm(acc8, 8, AH, 66, A_LO, SW, 65, 8320, 64, r0, g, t, chalf*64);
    #pragma unroll
    for (int n = 0; n < 8; n++) {
        int col = chalf*64 + n*8 + 2*t;
        int rA = r0 + g, rB = rA + 8;
        float v0 = fmaxf(acc8[n][0] + g_eg1b[(rA >> 3)*128 + col], 0.f);
        float v1 = fmaxf(acc8[n][1] + g_eg1b[(rA >> 3)*128 + col + 1], 0.f);
        float v2 = fmaxf(acc8[n][2] + g_eg1b[(rB >> 3)*128 + col], 0.f);
        float v3 = fmaxf(acc8[n][3] + g_eg1b[(rB >> 3)*128 + col + 1], 0.f);
        uint32 hi, lo;
        splitPack(v0, v1, hi, lo); AT1[rA*66 + col/2] = hi; AT1[A_LO + rA*66 + col/2] = lo;
        splitPack(v2, v3, hi, lo); AT1[rB*66 + col/2] = hi; AT1[A_LO + rB*66 + col/2] = lo;
    }

    // ---- Phase 4: out = a - g ----
    __syncthreads(); CPW(g_Ieg2, 4096, 6, 65, 4160); __syncthreads();
    #pragma unroll
    for (int n = 0; n < 4; n++) { acc4[n][0]=0;acc4[n][1]=0;acc4[n][2]=0;acc4[n][3]=0; }
    wgemm(acc4, 4, AT1, 66, A_LO, SW, 65, 4160, 64, r0, g, t, chalf*32);
    __syncthreads();   // AT1 reads done before sRN overwrites later
    #pragma unroll
    for (int n = 0; n < 4; n++) {
        int col = chalf*32 + n*8 + 2*t;
        int rA = r0 + g, rB = rA + 8;
        float o0 = sOf[rA*68 + col]     + acc4[n][0] - egB2[col];
        float o1 = sOf[rA*68 + col + 1] + acc4[n][1] - egB2[col + 1];
        float o2 = sOf[rB*68 + col]     + acc4[n][2] - egB2[col];
        float o3 = sOf[rB*68 + col + 1] + acc4[n][3] - egB2[col + 1];
        sOf[rA*68 + col] = o0; sOf[rA*68 + col + 1] = o1;
        sOf[rB*68 + col] = o2; sOf[rB*68 + col + 1] = o3;
        uint32 hi, lo;
        splitPack(o0, o1, hi, lo); AO[rA*34 + col/2] = hi; AO[AO_LO + rA*34 + col/2] = lo;
        splitPack(o2, o3, hi, lo); AO[rB*34 + col/2] = hi; AO[AO_LO + rB*34 + col/2] = lo;
    }
    __syncthreads();

    // ---- tension / softmax / numer ----
    if (tid < 64) {
        float s = 0.f;
        #pragma unroll 16
        for (int o = 0; o < 64; o++) { float v = sOf[tid*68 + o]; s = fmaf(v, v, s); }
        sTen[tid] = s * (1.f/64.f);
    }
    __syncthreads();
    if (tid < 8) {
        float s = 0.f;
        #pragma unroll
        for (int bb = 0; bb < 8; bb++) s += sTen[bb*8 + tid];
        float avg = s * 0.125f;
        sAvg[tid] = avg; sExp[tid] = expf(avg);
    }
    __syncthreads();
    if (tid < 64) {
        float v = 0.f;
        for (int ci = 0; ci < 8; ci++) {
            float co = 0.f;
            #pragma unroll
            for (int bb = 0; bb < 8; bb++)
                co = fmaf(sAabs[bb], sOf[(bb*8 + ci)*68 + tid], co);
            v = fmaf(sExp[ci], co, v);
        }
        atomicAdd(&g_numer[tid], v);
    } else if (tid == 64) {
        float se = 0.f, st = 0.f;
        for (int ci = 0; ci < 8; ci++) { se += sExp[ci]; st += sAvg[ci]; }
        atomicAdd(&g_denom, se); atomicAdd(&g_tsum, st);
    }
    __syncthreads();
    const float tenA = sTen[r0 + g], tenB = sTen[r0 + 8 + g];

    // ---- gate r ----
    CPW(g_Iwih[0], 4096, 5, 33, 4224); __syncthreads();
    #pragma unroll
    for (int n = 0; n < 8; n++) { acc8[n][0]=0;acc8[n][1]=0;acc8[n][2]=0;acc8[n][3]=0; }
    wgemm(acc8, 8, AO, 34, AO_LO, SW, 33, 4224, 32, r0, g, t, chalf*64);
    __syncthreads(); CPW(g_Iwhh[0], 8192, 6, 65, 8320); __syncthreads();
    wgemm(acc8, 8, AH, 66, A_LO, SW, 65, 8320, 64, r0, g, t, chalf*64);
    #pragma unroll
    for (int n = 0; n < 8; n++) {
        int u = chalf*64 + n*8 + 2*t;
        int rA = r0 + g, rB = rA + 8;
        sRN[rA*130 + u]     = 1.f/(1.f + expf(-(acc8[n][0] + bih[u] + bhh[u] + tenA*Wih[u*65 + 64])));
        sRN[rA*130 + u + 1] = 1.f/(1.f + expf(-(acc8[n][1] + bih[u+1] + bhh[u+1] + tenA*Wih[(u+1)*65 + 64])));
        sRN[rB*130 + u]     = 1.f/(1.f + expf(-(acc8[n][2] + bih[u] + bhh[u] + tenB*Wih[u*65 + 64])));
        sRN[rB*130 + u + 1] = 1.f/(1.f + expf(-(acc8[n][3] + bih[u+1] + bhh[u+1] + tenB*Wih[(u+1)*65 + 64])));
    }

    // ---- gate n ----
    float accI[8][4];
    __syncthreads(); CPW(g_Iwih[2], 4096, 5, 33, 4224); __syncthreads();
    #pragma unroll
    for (int n = 0; n < 8; n++) { accI[n][0]=0;accI[n][1]=0;accI[n][2]=0;accI[n][3]=0; }
    wgemm(accI, 8, AO, 34, AO_LO, SW, 33, 4224, 32, r0, g, t, chalf*64);
    __syncthreads(); CPW(g_Iwhh[2], 8192, 6, 65, 8320); __syncthreads();
    #pragma unroll
    for (int n = 0; n < 8; n++) { acc8[n][0]=0;acc8[n][1]=0;acc8[n][2]=0;acc8[n][3]=0; }
    wgemm(acc8, 8, AH, 66, A_LO, SW, 65, 8320, 64, r0, g, t, chalf*64);
    #pragma unroll
    for (int n = 0; n < 8; n++) {
        int u = chalf*64 + n*8 + 2*t;
        int rA = r0 + g, rB = rA + 8;
        #pragma unroll
        for (int j = 0; j < 2; j++) {
            int uu = 256 + u + j;
            float rrA = sRN[rA*130 + u + j];
            sRN[rA*130 + u + j] = tanhf(accI[n][j] + bih[uu] + tenA*Wih[uu*65 + 64]
                                        + rrA * (acc8[n][j] + bhh[uu]));
            float rrB = sRN[rB*130 + u + j];
            sRN[rB*130 + u + j] = tanhf(accI[n][2+j] + bih[uu] + tenB*Wih[uu*65 + 64]
                                        + rrB * (acc8[n][2+j] + bhh[uu]));
        }
    }

    // ---- gate z + combine ----
    __syncthreads(); CPW(g_Iwih[1], 4096, 5, 33, 4224); __syncthreads();
    #pragma unroll
    for (int n = 0; n < 8; n++) { acc8[n][0]=0;acc8[n][1]=0;acc8[n][2]=0;acc8[n][3]=0; }
    wgemm(acc8, 8, AO, 34, AO_LO, SW, 33, 4224, 32, r0, g, t, chalf*64);
    __syncthreads(); CPW(g_Iwhh[1], 8192, 6, 65, 8320); __syncthreads();
    wgemm(acc8, 8, AH, 66, A_LO, SW, 65, 8320, 64, r0, g, t, chalf*64);
    __syncthreads();   // all warps done with SW before sNew overwrite
    #pragma unroll
    for (int n = 0; n < 8; n++) {
        int u = chalf*64 + n*8 + 2*t;
        int rA = r0 + g, rB = rA + 8;
        float2 hA = unpackBf(AH[rA*66 + u/2], AH[A_LO + rA*66 + u/2]);
        float2 hB = unpackBf(AH[rB*66 + u/2], AH[A_LO + rB*66 + u/2]);
        #pragma unroll
        for (int j = 0; j < 2; j++) {
            int uu = 128 + u + j;
            float zA = 1.f/(1.f + expf(-(acc8[n][j] + bih[uu] + bhh[uu] + tenA*Wih[uu*65 + 64])));
            float zB = 1.f/(1.f + expf(-(acc8[n][2+j] + bih[uu] + bhh[uu] + tenB*Wih[uu*65 + 64])));
            float hAv = j ? hA.y : hA.x, hBv = j ? hB.y : hB.x;
            sNew[rA*130 + u + j] = (1.f - zA)*sRN[rA*130 + u + j] + zA*hAv;
            sNew[rB*130 + u + j] = (1.f - zB)*sRN[rB*130 + u + j] + zB*hBv;
        }
    }
    __syncthreads();

    // ---- faction sums + copy-out ----
    const int f = c0 >> 11;
    const bool deb = (c0 & 2047) < 512;
    for (int idx = tid; idx < 1024; idx += 256) {
        int b = idx >> 7, u = idx & 127;
        float s = 0.f;
        #pragma unroll
        for (int ci = 0; ci < 8; ci++) s += sNew[(b*8 + ci)*130 + u];
        atomicAdd(&g_fsum[(b*8 + f)*HIDD + u], s);
        if (deb) atomicAdd(&g_dsum[(b*8 + f)*HIDD + u], s);
    }
    for (int i = tid; i < 8192; i += 256) {
        int r = i >> 7, k = i & 127;
        out[nh_off + ((long long)((r >> 3)*NCC + c0 + (r & 7)))*HIDD + k] = sNew[r*130 + k];
    }
}

// ---------------- Stage C ----------------
__global__ void __launch_bounds__(256) stageC(
    const float* __restrict__ mixW, const float* __restrict__ mixb,
    const float* __restrict__ headW, const float* __restrict__ headb,
    const int* __restrict__ stepp, float* __restrict__ out, long long nh_off)
{
    __shared__ float sMF[NB*HIDD];
    __shared__ float sC[OUTD];
    int tid = threadIdx.x;
    int st = *stepp;
    for (int i = tid; i < NB*HIDD; i += 256) {
        int b = i >> 7, u = i & 127;
        float Sf = 0.f, Sd = 0.f;
        for (int f = 0; f < 8; f++) {
            float fsv = g_fsum[(b*8 + f)*HIDD + u];
            float fm = fsv * (1.f/2048.f);
            g_fm[(b*8 + f)*HIDD + u] = fm;
            Sf += fsv;
            Sd += 0.85f * g_dsum[(b*8 + f)*HIDD + u] + 76.8f * fm;
        }
        float m0 = Sf * (1.f/16384.f);
        g_m0[i] = m0;
        sMF[i] = (st > 5) ? (m0 + 0.15f * (0.25f*m0 - Sd * (1.f/16384.f))) : m0;
    }
    __syncthreads();
    if (tid < HIDD) {
        float v = mixb[tid];
        #pragma unroll 16
        for (int t = 0; t < NB*HIDD; t++) v = fmaf(sMF[t], mixW[tid*(NB*HIDD) + t], v);
        g_interf[tid] = v;
    }
    if (tid >= 128 && tid < 192) sC[tid - 128] = g_numer[tid - 128] / g_denom;
    __syncthreads();
    if (tid < OUTD) {
        float p = headb[tid];
        #pragma unroll
        for (int o = 0; o < OUTD; o++) p = fmaf(sC[o], headW[tid*OUTD + o], p);
        out[tid] = p;
    } else if (tid == 64) {
        out[nh_off - 1] = g_tsum * (1.f/16384.f);
    }
}

// ---------------- Stage D ----------------
__global__ void __launch_bounds__(256) stageD(const int* __restrict__ stepp,
                                              float* __restrict__ out, long long nh_off)
{
    long long idx = (long long)blockIdx.x*256 + threadIdx.x;
    int u = (int)(idx & 127);
    long long rc = idx >> 7;
    int c = (int)(rc & (NCC - 1));
    int b = (int)(rc >> 14);
    float v0 = out[nh_off + idx];
    int f = c >> 11;
    float v = 0.85f*v0 + 0.15f*g_fm[(b*8 + f)*HIDD + u];
    if (*stepp > 5 && (c & 2047) < 512) v = 0.85f*v + 0.15f*g_m0[b*HIDD + u];
    if (b == 0) v += 0.05f*g_interf[u];
    out[nh_off + idx] = v;
}

extern "C" void kernel_launch(void* const* d_in, const int* in_sizes, int n_in,
                              void* d_out, int out_size) {
    const float* x     = (const float*)d_in[0];
    const float* noise = (const float*)d_in[1];
    const float* amps  = (const float*)d_in[2];
    const float* hidd  = (const float*)d_in[3];
    const float* eaW1  = (const float*)d_in[4];
    const float* eaB1  = (const float*)d_in[5];
    const float* eaW2  = (const float*)d_in[6];
    const float* eaB2  = (const float*)d_in[7];
    const float* egW1  = (const float*)d_in[8];
    const float* egB1  = (const float*)d_in[9];
    const float* egW2  = (const float*)d_in[10];
    const float* egB2  = (const float*)d_in[11];
    const float* Wih   = (const float*)d_in[12];
    const float* Whh   = (const float*)d_in[13];
    const float* bih   = (const float*)d_in[14];
    const float* bhh   = (const float*)d_in[15];
    const float* headW = (const float*)d_in[16];
    const float* headb = (const float*)d_in[17];
    const float* mixW  = (const float*)d_in[18];
    const float* mixb  = (const float*)d_in[19];
    const int*   step  = (const int*)d_in[20];
    float* out = (float*)d_out;
    long long nh_off = (long long)out_size - (long long)NB*NCC*HIDD;

    cudaFuncSetAttribute(stageB, cudaFuncAttributeMaxDynamicSharedMemorySize, SMEM_B_BYTES);

    stageA<<<1, 256>>>(x, noise, amps, eaW1, eaB1, egW1, egB1);
    stageA2<<<96, 256>>>(eaW1, egW1, eaW2, egW2, Wih, Whh);
    stageB<<<NCC/8, 256, SMEM_B_BYTES>>>(hidd, Wih, bih, bhh, eaB2, egB2, out, nh_off);
    stageC<<<1, 256>>>(mixW, mixb, headW, headb, step, out, nh_off);
    stageD<<<(NB*NCC*HIDD)/256, 256>>>(step, out, nh_off);
}

// round 10
// speedup vs baseline: 2.1197x; 1.8777x over previous
#include <cuda_runtime.h>
#include <cuda_bf16.h>
#include <math.h>
#include <stdint.h>

#define NB 8
#define NCC 16384
#define HIDD 128
#define OUTD 64

typedef unsigned int uint32;

// ---- stage B smem byte offsets ----
#define AHB 1024
#define AT1B 66560
#define AOB 132096
#define SWB2 164864
#define SMEM_B_BYTES 197632

// ---------------- device scratch ----------------
__device__ float g_ea1b[NB*128];
__device__ float g_eg1b[NB*128];
__device__ float g_aabs[NB];
__device__ float g_fsum[NB*8*HIDD];
__device__ float g_dsum[NB*8*HIDD];
__device__ float g_fm[NB*8*HIDD];
__device__ float g_m0[NB*HIDD];
__device__ float g_interf[HIDD];
__device__ float g_numer[OUTD];
__device__ float g_denom, g_tsum;

// pre-swizzled bf16-pair weight images: hi block then lo block
__device__ __align__(16) uint32 g_Iea1[16384];
__device__ __align__(16) uint32 g_Ieg1[16384];
__device__ __align__(16) uint32 g_Iea2[8192];
__device__ __align__(16) uint32 g_Ieg2[8192];    // negated
__device__ __align__(16) uint32 g_Iwih[3][8192];
__device__ __align__(16) uint32 g_Iwhh[3][16384];

__device__ __forceinline__ void splitPack(float v0, float v1, uint32& hi, uint32& lo) {
    __nv_bfloat16 h0 = __float2bfloat16_rn(v0), h1 = __float2bfloat16_rn(v1);
    hi = (uint32)__bfloat16_as_ushort(h0) | ((uint32)__bfloat16_as_ushort(h1) << 16);
    __nv_bfloat16 l0 = __float2bfloat16_rn(v0 - __bfloat162float(h0));
    __nv_bfloat16 l1 = __float2bfloat16_rn(v1 - __bfloat162float(h1));
    lo = (uint32)__bfloat16_as_ushort(l0) | ((uint32)__bfloat16_as_ushort(l1) << 16);
}
__device__ __forceinline__ float2 unpackBf(uint32 hi, uint32 lo) {
    float a = __bfloat162float(__ushort_as_bfloat16((unsigned short)(hi & 0xFFFF)))
            + __bfloat162float(__ushort_as_bfloat16((unsigned short)(lo & 0xFFFF)));
    float b = __bfloat162float(__ushort_as_bfloat16((unsigned short)(hi >> 16)))
            + __bfloat162float(__ushort_as_bfloat16((unsigned short)(lo >> 16)));
    return make_float2(a, b);
}
__device__ __forceinline__ void mma_bf16(float* c, const uint32* a, uint32 b0, uint32 b1) {
    asm volatile("mma.sync.aligned.m16n8k16.row.col.f32.bf16.bf16.f32 "
        "{%0,%1,%2,%3}, {%4,%5,%6,%7}, {%8,%9}, {%0,%1,%2,%3};"
        : "+f"(c[0]), "+f"(c[1]), "+f"(c[2]), "+f"(c[3])
        : "r"(a[0]), "r"(a[1]), "r"(a[2]), "r"(a[3]), "r"(b0), "r"(b1));
}

// split-bf16 warp GEMM over XOR-swizzled pow2-stride tiles.
// hiStage: passes Ahi*W + Alo*W. loStage(false): Ahi*W (W = lo image staged).
__device__ __forceinline__ void wgemm(float (*acc)[4], int nT,
    const uint32* A, int saSh, int aLo, const uint32* W, int swSh,
    int k2, int r0, int g, int t, int nbase, bool hiStage)
{
    const int sw = g << 2;
    for (int kk = 0; kk < k2; kk += 8) {
        int c0i = (kk + t) ^ sw, c1i = (kk + t + 4) ^ sw;
        int ra0 = (r0 + g) << saSh, ra1 = (r0 + 8 + g) << saSh;
        uint32 ah[4] = { A[ra0 + c0i], A[ra1 + c0i], A[ra0 + c1i], A[ra1 + c1i] };
        uint32 al[4] = {0,0,0,0};
        if (hiStage) {
            al[0] = A[aLo + ra0 + c0i]; al[1] = A[aLo + ra1 + c0i];
            al[2] = A[aLo + ra0 + c1i]; al[3] = A[aLo + ra1 + c1i];
        }
        for (int nt = 0; nt < nT; nt++) {
            int wr = (nbase + nt*8 + g) << swSh;
            uint32 b0 = W[wr + c0i], b1 = W[wr + c1i];
            mma_bf16(acc[nt], ah, b0, b1);
            if (hiStage) mma_bf16(acc[nt], al, b0, b1);
        }
    }
}

// ---------------- Stage A ----------------
__global__ void __launch_bounds__(256) stageA(
    const float* __restrict__ x, const float* __restrict__ noise,
    const float* __restrict__ amps,
    const float* __restrict__ eaW1, const float* __restrict__ eaB1,
    const float* __restrict__ egW1, const float* __restrict__ egB1)
{
    __shared__ float sXB[NB*64];
    int tid = threadIdx.x;
    for (int i = tid; i < NB*8*HIDD; i += 256) { g_fsum[i] = 0.f; g_dsum[i] = 0.f; }
    if (tid < OUTD) g_numer[tid] = 0.f;
    if (tid == 0) {
        g_denom = 0.f; g_tsum = 0.f;
        float s = 1e-8f, t[NB];
        for (int b = 0; b < NB; b++) { t[b] = fabsf(amps[b]); s += t[b]; }
        for (int b = 0; b < NB; b++) g_aabs[b] = t[b] / s;
    }
    for (int i = tid; i < NB*64; i += 256) {
        int b = i >> 6, k = i & 63;
        sXB[i] = x[k] + noise[i] * 0.05f * (float)(b + 1);
    }
    __syncthreads();
    for (int i = tid; i < NB*128; i += 256) {
        int b = i >> 7, j = i & 127;
        float s1 = eaB1[j], s2 = egB1[j];
        const float* xb = sXB + b*64;
        #pragma unroll 8
        for (int k = 0; k < 64; k++) {
            s1 = fmaf(xb[k], eaW1[j*192 + k], s1);
            s2 = fmaf(xb[k], egW1[j*192 + k], s2);
        }
        g_ea1b[i] = s1; g_eg1b[i] = s2;
    }
}

// ---------------- Stage A2: pre-swizzled pair-packed images ----------------
__global__ void __launch_bounds__(256) stageA2(
    const float* __restrict__ eaW1, const float* __restrict__ egW1,
    const float* __restrict__ eaW2, const float* __restrict__ egW2,
    const float* __restrict__ Wih,  const float* __restrict__ Whh)
{
    int gt = blockIdx.x*256 + threadIdx.x, gs = gridDim.x*256;
    uint32 hi, lo;
    for (int i = gt; i < 8192; i += gs) {
        int j = i >> 6, cu = i & 63, k = 2*cu;
        int el = j*64 + (cu ^ ((j & 7) << 2));
        splitPack(eaW1[j*192 + 64 + k], eaW1[j*192 + 64 + k + 1], hi, lo);
        g_Iea1[el] = hi; g_Iea1[8192 + el] = lo;
        splitPack(egW1[j*192 + 64 + k], egW1[j*192 + 64 + k + 1], hi, lo);
        g_Ieg1[el] = hi; g_Ieg1[8192 + el] = lo;
    }
    for (int i = gt; i < 4096; i += gs) {
        int j = i >> 6, cu = i & 63, k = 2*cu;
        int el = j*64 + (cu ^ ((j & 7) << 2));
        splitPack(eaW2[j*128 + k], eaW2[j*128 + k + 1], hi, lo);
        g_Iea2[el] = hi; g_Iea2[4096 + el] = lo;
        splitPack(-egW2[j*128 + k], -egW2[j*128 + k + 1], hi, lo);
        g_Ieg2[el] = hi; g_Ieg2[4096 + el] = lo;
    }
    for (int gg = 0; gg < 3; gg++) {
        for (int i = gt; i < 4096; i += gs) {
            int j = i >> 5, cu = i & 31, k = 2*cu;
            int el = j*32 + (cu ^ ((j & 7) << 2));
            splitPack(Wih[(gg*128 + j)*65 + k], Wih[(gg*128 + j)*65 + k + 1], hi, lo);
            g_Iwih[gg][el] = hi; g_Iwih[gg][4096 + el] = lo;
        }
        for (int i = gt; i < 8192; i += gs) {
            int j = i >> 6, cu = i & 63, k = 2*cu;
            int el = j*64 + (cu ^ ((j & 7) << 2));
            splitPack(Whh[(gg*128 + j)*128 + k], Whh[(gg*128 + j)*128 + k + 1], hi, lo);
            g_Iwhh[gg][el] = hi; g_Iwhh[gg][8192 + el] = lo;
        }
    }
}

// ---------------- Stage B ----------------
__global__ void __launch_bounds__(512, 1) stageB(
    const float* __restrict__ hiddens, const float* __restrict__ Wih,
    const float* __restrict__ bih, const float* __restrict__ bhh,
    const float* __restrict__ eaB2, const float* __restrict__ egB2,
    float* __restrict__ out, long long nh_off)
{
    extern __shared__ char smem[];
    const int tid = threadIdx.x, wid = tid >> 5, lid = tid & 31;
    const int g = lid >> 2, t = lid & 3;
    const int rt = wid >> 1, chalf = wid & 1, r0 = rt * 16;
    const int c0 = blockIdx.x * 16;
    const int sw = g << 2;

    float* sTen = (float*)(smem);
    float* sAvg = (float*)(smem + 512);
    float* sExp = (float*)(smem + 576);
    float* sAabs = (float*)(smem + 640);
    uint32* AH  = (uint32*)(smem + AHB);
    uint32* AT1 = (uint32*)(smem + AT1B);
    uint32* AO  = (uint32*)(smem + AOB);
    uint32* SW  = (uint32*)(smem + SWB2);
    float*  sRN = (float*)(smem + AT1B);   // overlays AT1 after last AT1 use

    if (tid < 8) sAabs[tid] = g_aabs[tid];

    // build AH pair tile (128 rows x 64 k-pairs, swizzled)
    for (int i = tid; i < 8192; i += 512) {
        int r = i >> 6, cu = i & 63;
        const float* hp = hiddens + ((long long)((r >> 4)*NCC + c0 + (r & 15)))*HIDD + 2*cu;
        uint32 hi, lo; splitPack(hp[0], hp[1], hi, lo);
        int el = r*64 + (cu ^ ((r & 7) << 2));
        AH[el] = hi; AH[8192 + el] = lo;
    }

#define GEMM_STAGED(acc, nT, Abuf, saSh, aLo, img, nWords, swSh, k2, nbase) { \
    __syncthreads(); \
    { const float4* _s = (const float4*)(img); float4* _d = (float4*)SW; \
      for (int _i = tid; _i*4 < (nWords); _i += 512) _d[_i] = _s[_i]; } \
    __syncthreads(); \
    wgemm(acc, nT, Abuf, saSh, aLo, SW, swSh, k2, r0, g, t, nbase, true); \
    __syncthreads(); \
    { const float4* _s = (const float4*)((img) + (nWords)); float4* _d = (float4*)SW; \
      for (int _i = tid; _i*4 < (nWords); _i += 512) _d[_i] = _s[_i]; } \
    __syncthreads(); \
    wgemm(acc, nT, Abuf, saSh, aLo, SW, swSh, k2, r0, g, t, nbase, false); \
}
#define ZACC(a, n) { _Pragma("unroll") for (int _n = 0; _n < (n); _n++) { (a)[_n][0]=0;(a)[_n][1]=0;(a)[_n][2]=0;(a)[_n][3]=0; } }

    float acc8[8][4], accA[4][4], accG[4][4];
    const int rA = r0 + g, rB = r0 + 8 + g;

    // P1: t1a = relu(H @ eaW1h^T + biasA)
    ZACC(acc8, 8);
    GEMM_STAGED(acc8, 8, AH, 6, 8192, g_Iea1, 8192, 6, 64, chalf*64);
    #pragma unroll
    for (int n = 0; n < 8; n++) {
        int col = chalf*64 + n*8 + 2*t;
        float b0 = g_ea1b[rt*128 + col], b1 = g_ea1b[rt*128 + col + 1];
        float v0 = fmaxf(acc8[n][0] + b0, 0.f), v1 = fmaxf(acc8[n][1] + b1, 0.f);
        float v2 = fmaxf(acc8[n][2] + b0, 0.f), v3 = fmaxf(acc8[n][3] + b1, 0.f);
        int cu = col >> 1;
        int elA = rA*64 + (cu ^ sw), elB = rB*64 + (cu ^ sw);
        uint32 hi, lo;
        splitPack(v0, v1, hi, lo); AT1[elA] = hi; AT1[8192 + elA] = lo;
        splitPack(v2, v3, hi, lo); AT1[elB] = hi; AT1[8192 + elB] = lo;
    }

    // P2: a = t1a @ eaW2^T (raw, biases added in P4)
    ZACC(accA, 4);
    GEMM_STAGED(accA, 4, AT1, 6, 8192, g_Iea2, 4096, 6, 64, chalf*32);

    // P3: t1g
    ZACC(acc8, 8);
    GEMM_STAGED(acc8, 8, AH, 6, 8192, g_Ieg1, 8192, 6, 64, chalf*64);
    #pragma unroll
    for (int n = 0; n < 8; n++) {
        int col = chalf*64 + n*8 + 2*t;
        float b0 = g_eg1b[rt*128 + col], b1 = g_eg1b[rt*128 + col + 1];
        float v0 = fmaxf(acc8[n][0] + b0, 0.f), v1 = fmaxf(acc8[n][1] + b1, 0.f);
        float v2 = fmaxf(acc8[n][2] + b0, 0.f), v3 = fmaxf(acc8[n][3] + b1, 0.f);
        int cu = col >> 1;
        int elA = rA*64 + (cu ^ sw), elB = rB*64 + (cu ^ sw);
        uint32 hi, lo;
        splitPack(v0, v1, hi, lo); AT1[elA] = hi; AT1[8192 + elA] = lo;
        splitPack(v2, v3, hi, lo); AT1[elB] = hi; AT1[8192 + elB] = lo;
    }

    // P4: out = a - g  (eg2 image pre-negated)
    ZACC(accG, 4);
    GEMM_STAGED(accG, 4, AT1, 6, 8192, g_Ieg2, 4096, 6, 64, chalf*32);
    #pragma unroll
    for (int n = 0; n < 4; n++) {
        int col = chalf*32 + n*8 + 2*t;
        float e0 = eaB2[col] - egB2[col], e1 = eaB2[col+1] - egB2[col+1];
        float o0 = accA[n][0] + accG[n][0] + e0, o1 = accA[n][1] + accG[n][1] + e1;
        float o2 = accA[n][2] + accG[n][2] + e0, o3 = accA[n][3] + accG[n][3] + e1;
        int cu = col >> 1;
        int elA = rA*32 + (cu ^ sw), elB = rB*32 + (cu ^ sw);
        uint32 hi, lo;
        splitPack(o0, o1, hi, lo); AO[elA] = hi; AO[4096 + elA] = lo;
        splitPack(o2, o3, hi, lo); AO[elB] = hi; AO[4096 + elB] = lo;
    }
    __syncthreads();

    // tension per row
    if (tid < 128) {
        int row = tid; float s = 0.f;
        int rsw = (row & 7) << 2;
        #pragma unroll 8
        for (int cu = 0; cu < 32; cu++) {
            int el = row*32 + (cu ^ rsw);
            float2 p = unpackBf(AO[el], AO[4096 + el]);
            s = fmaf(p.x, p.x, s); s = fmaf(p.y, p.y, s);
        }
        sTen[row] = s * (1.f/64.f);
    }
    __syncthreads();
    if (tid < 16) {
        float s = 0.f;
        #pragma unroll
        for (int b = 0; b < 8; b++) s += sTen[b*16 + tid];
        float avg = s * 0.125f;
        sAvg[tid] = avg; sExp[tid] = expf(avg);
    }
    __syncthreads();
    if (tid < 64) {
        int cu = tid >> 1; float v = 0.f;
        for (int ci = 0; ci < 16; ci++) {
            float co = 0.f;
            #pragma unroll
            for (int b = 0; b < 8; b++) {
                int r = b*16 + ci;
                int el = r*32 + (cu ^ ((r & 7) << 2));
                float2 p = unpackBf(AO[el], AO[4096 + el]);
                co = fmaf(sAabs[b], (tid & 1) ? p.y : p.x, co);
            }
            v = fmaf(sExp[ci], co, v);
        }
        atomicAdd(&g_numer[tid], v);
    } else if (tid == 64) {
        float se = 0.f, st = 0.f;
        for (int ci = 0; ci < 16; ci++) { se += sExp[ci]; st += sAvg[ci]; }
        atomicAdd(&g_denom, se); atomicAdd(&g_tsum, st);
    }
    const float tenA = sTen[rA], tenB = sTen[rB];

    // gate r
    ZACC(acc8, 8);
    GEMM_STAGED(acc8, 8, AO, 5, 4096, g_Iwih[0], 4096, 5, 32, chalf*64);
    GEMM_STAGED(acc8, 8, AH, 6, 8192, g_Iwhh[0], 8192, 6, 64, chalf*64);
    #pragma unroll
    for (int n = 0; n < 8; n++) {
        int u = chalf*64 + n*8 + 2*t;
        int pA = rA*128 + (u ^ sw), pB = rB*128 + (u ^ sw);
        sRN[pA]     = 1.f/(1.f + expf(-(acc8[n][0] + bih[u] + bhh[u] + tenA*Wih[u*65 + 64])));
        sRN[pA + 1] = 1.f/(1.f + expf(-(acc8[n][1] + bih[u+1] + bhh[u+1] + tenA*Wih[(u+1)*65 + 64])));
        sRN[pB]     = 1.f/(1.f + expf(-(acc8[n][2] + bih[u] + bhh[u] + tenB*Wih[u*65 + 64])));
        sRN[pB + 1] = 1.f/(1.f + expf(-(acc8[n][3] + bih[u+1] + bhh[u+1] + tenB*Wih[(u+1)*65 + 64])));
    }

    // gate n (inn from AO@wih2, hn from AH@whh2) -> n in place of r
    float accI[8][4];
    ZACC(accI, 8);
    GEMM_STAGED(accI, 8, AO, 5, 4096, g_Iwih[2], 4096, 5, 32, chalf*64);
    ZACC(acc8, 8);
    GEMM_STAGED(acc8, 8, AH, 6, 8192, g_Iwhh[2], 8192, 6, 64, chalf*64);
    #pragma unroll
    for (int n = 0; n < 8; n++) {
        int u = chalf*64 + n*8 + 2*t;
        int pA = rA*128 + (u ^ sw), pB = rB*128 + (u ^ sw);
        #pragma unroll
        for (int j = 0; j < 2; j++) {
            int uu = 256 + u + j;
            float rrA = sRN[pA + j];
            sRN[pA + j] = tanhf(accI[n][j] + bih[uu] + tenA*Wih[uu*65 + 64]
                                + rrA * (acc8[n][j] + bhh[uu]));
            float rrB = sRN[pB + j];
            sRN[pB + j] = tanhf(accI[n][2+j] + bih[uu] + tenB*Wih[uu*65 + 64]
                                + rrB * (acc8[n][2+j] + bhh[uu]));
        }
    }

    // gate z + combine -> newh (in place)
    ZACC(acc8, 8);
    GEMM_STAGED(acc8, 8, AO, 5, 4096, g_Iwih[1], 4096, 5, 32, chalf*64);
    GEMM_STAGED(acc8, 8, AH, 6, 8192, g_Iwhh[1], 8192, 6, 64, chalf*64);
    #pragma unroll
    for (int n = 0; n < 8; n++) {
        int u = chalf*64 + n*8 + 2*t;
        int cu = u >> 1;
        int pA = rA*128 + (u ^ sw), pB = rB*128 + (u ^ sw);
        int eA = rA*64 + (cu ^ sw), eB = rB*64 + (cu ^ sw);
        float2 hA = unpackBf(AH[eA], AH[8192 + eA]);
        float2 hB = unpackBf(AH[eB], AH[8192 + eB]);
        #pragma unroll
        for (int j = 0; j < 2; j++) {
            int uu = 128 + u + j;
            float zA = 1.f/(1.f + expf(-(acc8[n][j] + bih[uu] + bhh[uu] + tenA*Wih[uu*65 + 64])));
            float zB = 1.f/(1.f + expf(-(acc8[n][2+j] + bih[uu] + bhh[uu] + tenB*Wih[uu*65 + 64])));
            float hAv = j ? hA.y : hA.x, hBv = j ? hB.y : hB.x;
            sRN[pA + j] = (1.f - zA)*sRN[pA + j] + zA*hAv;
            sRN[pB + j] = (1.f - zB)*sRN[pB + j] + zB*hBv;
        }
    }
    __syncthreads();

    // faction sums + copy-out
    const int f = c0 >> 11;
    const bool deb = (c0 & 2047) < 512;
    for (int idx = tid; idx < 1024; idx += 512) {
        int b = idx >> 7, u = idx & 127;
        float s = 0.f;
        #pragma unroll
        for (int ci = 0; ci < 16; ci++)
            s += sRN[(b*16 + ci)*128 + (u ^ ((ci & 7) << 2))];
        atomicAdd(&g_fsum[(b*8 + f)*HIDD + u], s);
        if (deb) atomicAdd(&g_dsum[(b*8 + f)*HIDD + u], s);
    }
    for (int i = tid; i < 16384; i += 512) {
        int r = i >> 7, k = i & 127;
        out[nh_off + ((long long)((r >> 4)*NCC + c0 + (r & 15)))*HIDD + k]
            = sRN[r*128 + (k ^ ((r & 7) << 2))];
    }
}

// ---------------- Stage C ----------------
__global__ void __launch_bounds__(1024) stageC(
    const float* __restrict__ mixW, const float* __restrict__ mixb,
    const float* __restrict__ headW, const float* __restrict__ headb,
    const int* __restrict__ stepp, float* __restrict__ out, long long nh_off)
{
    __shared__ float sMF[NB*HIDD];
    __shared__ float sPart[1024];
    __shared__ float sC[OUTD];
    int tid = threadIdx.x;
    int st = *stepp;
    {
        int b = tid >> 7, u = tid & 127;
        float Sf = 0.f, Sd = 0.f;
        for (int f = 0; f < 8; f++) {
            float fsv = g_fsum[(b*8 + f)*HIDD + u];
            float fm = fsv * (1.f/2048.f);
            g_fm[(b*8 + f)*HIDD + u] = fm;
            Sf += fsv;
            Sd += 0.85f * g_dsum[(b*8 + f)*HIDD + u] + 76.8f * fm;
        }
        float m0 = Sf * (1.f/16384.f);
        g_m0[tid] = m0;
        sMF[tid] = (st > 5) ? (m0 + 0.15f * (0.25f*m0 - Sd * (1.f/16384.f))) : m0;
    }
    __syncthreads();
    {
        int u = tid >> 3, p = tid & 7;
        float s = 0.f;
        const float* wrow = mixW + u*1024 + p*128;
        const float* mrow = sMF + p*128;
        #pragma unroll 8
        for (int i = 0; i < 128; i++) s = fmaf(mrow[i], wrow[i], s);
        sPart[tid] = s;
    }
    __syncthreads();
    if (tid < 128) {
        float v = mixb[tid];
        #pragma unroll
        for (int j = 0; j < 8; j++) v += sPart[tid*8 + j];
        g_interf[tid] = v;
    }
    if (tid >= 256 && tid < 320) sC[tid - 256] = g_numer[tid - 256] / g_denom;
    __syncthreads();
    if (tid < OUTD) {
        float p = headb[tid];
        #pragma unroll
        for (int o = 0; o < OUTD; o++) p = fmaf(sC[o], headW[tid*OUTD + o], p);
        out[tid] = p;
    } else if (tid == 64) {
        out[nh_off - 1] = g_tsum * (1.f/16384.f);
    }
}

// ---------------- Stage D (4 elems/thread) ----------------
__global__ void __launch_bounds__(256) stageD(const int* __restrict__ stepp,
                                              float* __restrict__ out, long long nh_off)
{
    long long base = ((long long)blockIdx.x*256 + threadIdx.x) * 4;
    int u = (int)(base & 127);
    long long rc = base >> 7;
    int c = (int)(rc & (NCC - 1));
    int b = (int)(rc >> 14);
    int f = c >> 11;
    bool dbg = (*stepp > 5) && ((c & 2047) < 512);
    float* p = out + nh_off + base;
    const float* fm = g_fm + (b*8 + f)*HIDD + u;
    const float* m0 = g_m0 + b*HIDD + u;
    const float* itf = g_interf + u;
    #pragma unroll
    for (int j = 0; j < 4; j++) {
        float v = 0.85f*p[j] + 0.15f*fm[j];
        if (dbg) v = 0.85f*v + 0.15f*m0[j];
        if (b == 0) v += 0.05f*itf[j];
        p[j] = v;
    }
}

extern "C" void kernel_launch(void* const* d_in, const int* in_sizes, int n_in,
                              void* d_out, int out_size) {
    const float* x     = (const float*)d_in[0];
    const float* noise = (const float*)d_in[1];
    const float* amps  = (const float*)d_in[2];
    const float* hidd  = (const float*)d_in[3];
    const float* eaW1  = (const float*)d_in[4];
    const float* eaB1  = (const float*)d_in[5];
    const float* eaW2  = (const float*)d_in[6];
    const float* eaB2  = (const float*)d_in[7];
    const float* egW1  = (const float*)d_in[8];
    const float* egB1  = (const float*)d_in[9];
    const float* egW2  = (const float*)d_in[10];
    const float* egB2  = (const float*)d_in[11];
    const float* Wih   = (const float*)d_in[12];
    const float* Whh   = (const float*)d_in[13];
    const float* bih   = (const float*)d_in[14];
    const float* bhh   = (const float*)d_in[15];
    const float* headW = (const float*)d_in[16];
    const float* headb = (const float*)d_in[17];
    const float* mixW  = (const float*)d_in[18];
    const float* mixb  = (const float*)d_in[19];
    const int*   step  = (const int*)d_in[20];
    float* out = (float*)d_out;
    long long nh_off = (long long)out_size - (long long)NB*NCC*HIDD;

    cudaFuncSetAttribute(stageB, cudaFuncAttributeMaxDynamicSharedMemorySize, SMEM_B_BYTES);

    stageA<<<1, 256>>>(x, noise, amps, eaW1, eaB1, egW1, egB1);
    stageA2<<<96, 256>>>(eaW1, egW1, eaW2, egW2, Wih, Whh);
    stageB<<<NCC/16, 512, SMEM_B_BYTES>>>(hidd, Wih, bih, bhh, eaB2, egB2, out, nh_off);
    stageC<<<1, 1024>>>(mixW, mixb, headW, headb, step, out, nh_off);
    stageD<<<(NB*NCC*HIDD)/1024, 256>>>(step, out, nh_off);
}

// round 14
// speedup vs baseline: 2.3986x; 1.1316x over previous
#include <cuda_runtime.h>
#include <cuda_bf16.h>
#include <math.h>
#include <stdint.h>

#define NB 8
#define NCC 16384
#define HIDD 128
#define OUTD 64

typedef unsigned int uint32;

// ---- stage B smem byte offsets (known-good R10 layout) ----
#define AHB 1024
#define AT1B 66560
#define AOB 132096
#define SWB2 164864
#define SMEM_B_BYTES 197632

// ---------------- device scratch ----------------
__device__ float g_ea1b[NB*128];
__device__ float g_eg1b[NB*128];
__device__ float g_aabs[NB];
__device__ float g_fsum[NB*8*HIDD];
__device__ float g_dsum[NB*8*HIDD];
__device__ float g_fm[NB*8*HIDD];
__device__ float g_m0[NB*HIDD];
__device__ float g_interf[HIDD];
__device__ float g_numer[OUTD];
__device__ float g_denom, g_tsum;

// pre-swizzled bf16-pair weight images: hi block then lo block
__device__ __align__(16) uint32 g_Iea1[16384];
__device__ __align__(16) uint32 g_Ieg1[16384];
__device__ __align__(16) uint32 g_Iea2[8192];
__device__ __align__(16) uint32 g_Ieg2[8192];    // negated
__device__ __align__(16) uint32 g_Iwih[3][8192];
__device__ __align__(16) uint32 g_Iwhh[3][16384];

__device__ __forceinline__ void splitPack(float v0, float v1, uint32& hi, uint32& lo) {
    __nv_bfloat16 h0 = __float2bfloat16_rn(v0), h1 = __float2bfloat16_rn(v1);
    hi = (uint32)__bfloat16_as_ushort(h0) | ((uint32)__bfloat16_as_ushort(h1) << 16);
    __nv_bfloat16 l0 = __float2bfloat16_rn(v0 - __bfloat162float(h0));
    __nv_bfloat16 l1 = __float2bfloat16_rn(v1 - __bfloat162float(h1));
    lo = (uint32)__bfloat16_as_ushort(l0) | ((uint32)__bfloat16_as_ushort(l1) << 16);
}
__device__ __forceinline__ float2 unpackBf(uint32 hi, uint32 lo) {
    float a = __bfloat162float(__ushort_as_bfloat16((unsigned short)(hi & 0xFFFF)))
            + __bfloat162float(__ushort_as_bfloat16((unsigned short)(lo & 0xFFFF)));
    float b = __bfloat162float(__ushort_as_bfloat16((unsigned short)(hi >> 16)))
            + __bfloat162float(__ushort_as_bfloat16((unsigned short)(lo >> 16)));
    return make_float2(a, b);
}
__device__ __forceinline__ void mma_bf16(float* c, const uint32* a, uint32 b0, uint32 b1) {
    asm volatile("mma.sync.aligned.m16n8k16.row.col.f32.bf16.bf16.f32 "
        "{%0,%1,%2,%3}, {%4,%5,%6,%7}, {%8,%9}, {%0,%1,%2,%3};"
        : "+f"(c[0]), "+f"(c[1]), "+f"(c[2]), "+f"(c[3])
        : "r"(a[0]), "r"(a[1]), "r"(a[2]), "r"(a[3]), "r"(b0), "r"(b1));
}
__device__ __forceinline__ float fsigm(float x) { return 1.f / (1.f + __expf(-x)); }
__device__ __forceinline__ float ftanh(float x) {
    float y; asm("tanh.approx.f32 %0, %1;" : "=f"(y) : "f"(x)); return y;
}

// split-bf16 warp GEMM over XOR-swizzled pow2-stride tiles (R10 two-stage form).
// hiStage: passes Ahi*W + Alo*W. loStage(false): Ahi*W (W = lo image staged).
__device__ __forceinline__ void wgemm(float (*acc)[4], int nT,
    const uint32* A, int saSh, int aLo, const uint32* W, int swSh,
    int k2, int r0, int g, int t, int nbase, bool hiStage)
{
    const int sw = g << 2;
    for (int kk = 0; kk < k2; kk += 8) {
        int c0i = (kk + t) ^ sw, c1i = (kk + t + 4) ^ sw;
        int ra0 = (r0 + g) << saSh, ra1 = (r0 + 8 + g) << saSh;
        uint32 ah[4] = { A[ra0 + c0i], A[ra1 + c0i], A[ra0 + c1i], A[ra1 + c1i] };
        uint32 al[4] = {0,0,0,0};
        if (hiStage) {
            al[0] = A[aLo + ra0 + c0i]; al[1] = A[aLo + ra1 + c0i];
            al[2] = A[aLo + ra0 + c1i]; al[3] = A[aLo + ra1 + c1i];
        }
        for (int nt = 0; nt < nT; nt++) {
            int wr = (nbase + nt*8 + g) << swSh;
            uint32 b0 = W[wr + c0i], b1 = W[wr + c1i];
            mma_bf16(acc[nt], ah, b0, b1);
            if (hiStage) mma_bf16(acc[nt], al, b0, b1);
        }
    }
}

// ---------------- Stage A ----------------
__global__ void __launch_bounds__(256) stageA(
    const float* __restrict__ x, const float* __restrict__ noise,
    const float* __restrict__ amps,
    const float* __restrict__ eaW1, const float* __restrict__ eaB1,
    const float* __restrict__ egW1, const float* __restrict__ egB1)
{
    __shared__ float sXB[NB*64];
    int tid = threadIdx.x;
    for (int i = tid; i < NB*8*HIDD; i += 256) { g_fsum[i] = 0.f; g_dsum[i] = 0.f; }
    if (tid < OUTD) g_numer[tid] = 0.f;
    if (tid == 0) {
        g_denom = 0.f; g_tsum = 0.f;
        float s = 1e-8f, t[NB];
        for (int b = 0; b < NB; b++) { t[b] = fabsf(amps[b]); s += t[b]; }
        for (int b = 0; b < NB; b++) g_aabs[b] = t[b] / s;
    }
    for (int i = tid; i < NB*64; i += 256) {
        int b = i >> 6, k = i & 63;
        sXB[i] = x[k] + noise[i] * 0.05f * (float)(b + 1);
    }
    __syncthreads();
    for (int i = tid; i < NB*128; i += 256) {
        int b = i >> 7, j = i & 127;
        float s1 = eaB1[j], s2 = egB1[j];
        const float* xb = sXB + b*64;
        #pragma unroll 8
        for (int k = 0; k < 64; k++) {
            s1 = fmaf(xb[k], eaW1[j*192 + k], s1);
            s2 = fmaf(xb[k], egW1[j*192 + k], s2);
        }
        g_ea1b[i] = s1; g_eg1b[i] = s2;
    }
}

// ---------------- Stage A2: pre-swizzled pair-packed images ----------------
__global__ void __launch_bounds__(256) stageA2(
    const float* __restrict__ eaW1, const float* __restrict__ egW1,
    const float* __restrict__ eaW2, const float* __restrict__ egW2,
    const float* __restrict__ Wih,  const float* __restrict__ Whh)
{
    int gt = blockIdx.x*256 + threadIdx.x, gs = gridDim.x*256;
    uint32 hi, lo;
    for (int i = gt; i < 8192; i += gs) {
        int j = i >> 6, cu = i & 63, k = 2*cu;
        int el = j*64 + (cu ^ ((j & 7) << 2));
        splitPack(eaW1[j*192 + 64 + k], eaW1[j*192 + 64 + k + 1], hi, lo);
        g_Iea1[el] = hi; g_Iea1[8192 + el] = lo;
        splitPack(egW1[j*192 + 64 + k], egW1[j*192 + 64 + k + 1], hi, lo);
        g_Ieg1[el] = hi; g_Ieg1[8192 + el] = lo;
    }
    for (int i = gt; i < 4096; i += gs) {
        int j = i >> 6, cu = i & 63, k = 2*cu;
        int el = j*64 + (cu ^ ((j & 7) << 2));
        splitPack(eaW2[j*128 + k], eaW2[j*128 + k + 1], hi, lo);
        g_Iea2[el] = hi; g_Iea2[4096 + el] = lo;
        splitPack(-egW2[j*128 + k], -egW2[j*128 + k + 1], hi, lo);
        g_Ieg2[el] = hi; g_Ieg2[4096 + el] = lo;
    }
    for (int gg = 0; gg < 3; gg++) {
        for (int i = gt; i < 4096; i += gs) {
            int j = i >> 5, cu = i & 31, k = 2*cu;
            int el = j*32 + (cu ^ ((j & 7) << 2));
            splitPack(Wih[(gg*128 + j)*65 + k], Wih[(gg*128 + j)*65 + k + 1], hi, lo);
            g_Iwih[gg][el] = hi; g_Iwih[gg][4096 + el] = lo;
        }
        for (int i = gt; i < 8192; i += gs) {
            int j = i >> 6, cu = i & 63, k = 2*cu;
            int el = j*64 + (cu ^ ((j & 7) << 2));
            splitPack(Whh[(gg*128 + j)*128 + k], Whh[(gg*128 + j)*128 + k + 1], hi, lo);
            g_Iwhh[gg][el] = hi; g_Iwhh[gg][8192 + el] = lo;
        }
    }
}

// ---------------- Stage B ----------------
__global__ void __launch_bounds__(512, 1) stageB(
    const float* __restrict__ hiddens, const float* __restrict__ Wih,
    const float* __restrict__ bih, const float* __restrict__ bhh,
    const float* __restrict__ eaB2, const float* __restrict__ egB2,
    float* __restrict__ out, long long nh_off)
{
    extern __shared__ char smem[];
    const int tid = threadIdx.x, wid = tid >> 5, lid = tid & 31;
    const int g = lid >> 2, t = lid & 3;
    const int rt = wid >> 1, chalf = wid & 1, r0 = rt * 16;
    const int c0 = blockIdx.x * 16;
    const int sw = g << 2;

    float* sTen = (float*)(smem);
    float* sAvg = (float*)(smem + 512);
    float* sExp = (float*)(smem + 576);
    float* sAabs = (float*)(smem + 640);
    uint32* AH  = (uint32*)(smem + AHB);
    uint32* AT1 = (uint32*)(smem + AT1B);
    uint32* AO  = (uint32*)(smem + AOB);
    uint32* SW  = (uint32*)(smem + SWB2);
    float*  sRN = (float*)(smem + AT1B);   // overlays AT1 after last AT1 use

    if (tid < 8) sAabs[tid] = g_aabs[tid];

    // build AH pair tile (128 rows x 64 k-pairs, swizzled)
    for (int i = tid; i < 8192; i += 512) {
        int r = i >> 6, cu = i & 63;
        const float* hp = hiddens + ((long long)((r >> 4)*NCC + c0 + (r & 15)))*HIDD + 2*cu;
        uint32 hi, lo; splitPack(hp[0], hp[1], hi, lo);
        int el = r*64 + (cu ^ ((r & 7) << 2));
        AH[el] = hi; AH[8192 + el] = lo;
    }

#define GEMM_STAGED(acc, nT, Abuf, saSh, aLo, img, nWords, swSh, k2, nbase) { \
    __syncthreads(); \
    { const float4* _s = (const float4*)(img); float4* _d = (float4*)SW; \
      for (int _i = tid; _i*4 < (nWords); _i += 512) _d[_i] = _s[_i]; } \
    __syncthreads(); \
    wgemm(acc, nT, Abuf, saSh, aLo, SW, swSh, k2, r0, g, t, nbase, true); \
    __syncthreads(); \
    { const float4* _s = (const float4*)((img) + (nWords)); float4* _d = (float4*)SW; \
      for (int _i = tid; _i*4 < (nWords); _i += 512) _d[_i] = _s[_i]; } \
    __syncthreads(); \
    wgemm(acc, nT, Abuf, saSh, aLo, SW, swSh, k2, r0, g, t, nbase, false); \
}
#define ZACC(a, n) { _Pragma("unroll") for (int _n = 0; _n < (n); _n++) { (a)[_n][0]=0;(a)[_n][1]=0;(a)[_n][2]=0;(a)[_n][3]=0; } }

    float acc8[8][4], accA[4][4], accG[4][4];
    const int rA = r0 + g, rB = r0 + 8 + g;

    // P1: t1a = relu(H @ eaW1h^T + biasA)
    ZACC(acc8, 8);
    GEMM_STAGED(acc8, 8, AH, 6, 8192, g_Iea1, 8192, 6, 64, chalf*64);
    #pragma unroll
    for (int n = 0; n < 8; n++) {
        int col = chalf*64 + n*8 + 2*t;
        float b0 = g_ea1b[rt*128 + col], b1 = g_ea1b[rt*128 + col + 1];
        float v0 = fmaxf(acc8[n][0] + b0, 0.f), v1 = fmaxf(acc8[n][1] + b1, 0.f);
        float v2 = fmaxf(acc8[n][2] + b0, 0.f), v3 = fmaxf(acc8[n][3] + b1, 0.f);
        int cu = col >> 1;
        int elA = rA*64 + (cu ^ sw), elB = rB*64 + (cu ^ sw);
        uint32 hi, lo;
        splitPack(v0, v1, hi, lo); AT1[elA] = hi; AT1[8192 + elA] = lo;
        splitPack(v2, v3, hi, lo); AT1[elB] = hi; AT1[8192 + elB] = lo;
    }

    // P2: a = t1a @ eaW2^T (raw, biases added in P4)
    ZACC(accA, 4);
    GEMM_STAGED(accA, 4, AT1, 6, 8192, g_Iea2, 4096, 6, 64, chalf*32);

    // P3: t1g
    ZACC(acc8, 8);
    GEMM_STAGED(acc8, 8, AH, 6, 8192, g_Ieg1, 8192, 6, 64, chalf*64);
    #pragma unroll
    for (int n = 0; n < 8; n++) {
        int col = chalf*64 + n*8 + 2*t;
        float b0 = g_eg1b[rt*128 + col], b1 = g_eg1b[rt*128 + col + 1];
        float v0 = fmaxf(acc8[n][0] + b0, 0.f), v1 = fmaxf(acc8[n][1] + b1, 0.f);
        float v2 = fmaxf(acc8[n][2] + b0, 0.f), v3 = fmaxf(acc8[n][3] + b1, 0.f);
        int cu = col >> 1;
        int elA = rA*64 + (cu ^ sw), elB = rB*64 + (cu ^ sw);
        uint32 hi, lo;
        splitPack(v0, v1, hi, lo); AT1[elA] = hi; AT1[8192 + elA] = lo;
        splitPack(v2, v3, hi, lo); AT1[elB] = hi; AT1[8192 + elB] = lo;
    }

    // P4: out = a - g  (eg2 image pre-negated)
    ZACC(accG, 4);
    GEMM_STAGED(accG, 4, AT1, 6, 8192, g_Ieg2, 4096, 6, 64, chalf*32);
    #pragma unroll
    for (int n = 0; n < 4; n++) {
        int col = chalf*32 + n*8 + 2*t;
        float e0 = eaB2[col] - egB2[col], e1 = eaB2[col+1] - egB2[col+1];
        float o0 = accA[n][0] + accG[n][0] + e0, o1 = accA[n][1] + accG[n][1] + e1;
        float o2 = accA[n][2] + accG[n][2] + e0, o3 = accA[n][3] + accG[n][3] + e1;
        int cu = col >> 1;
        int elA = rA*32 + (cu ^ sw), elB = rB*32 + (cu ^ sw);
        uint32 hi, lo;
        splitPack(o0, o1, hi, lo); AO[elA] = hi; AO[4096 + elA] = lo;
        splitPack(o2, o3, hi, lo); AO[elB] = hi; AO[4096 + elB] = lo;
    }
    __syncthreads();

    // tension per row
    if (tid < 128) {
        int row = tid; float s = 0.f;
        int rsw = (row & 7) << 2;
        #pragma unroll 8
        for (int cu = 0; cu < 32; cu++) {
            int el = row*32 + (cu ^ rsw);
            float2 p = unpackBf(AO[el], AO[4096 + el]);
            s = fmaf(p.x, p.x, s); s = fmaf(p.y, p.y, s);
        }
        sTen[row] = s * (1.f/64.f);
    }
    __syncthreads();
    if (tid < 16) {
        float s = 0.f;
        #pragma unroll
        for (int b = 0; b < 8; b++) s += sTen[b*16 + tid];
        float avg = s * 0.125f;
        sAvg[tid] = avg; sExp[tid] = __expf(avg);
    }
    __syncthreads();
    if (tid < 64) {
        int cu = tid >> 1; float v = 0.f;
        for (int ci = 0; ci < 16; ci++) {
            float co = 0.f;
            #pragma unroll
            for (int b = 0; b < 8; b++) {
                int r = b*16 + ci;
                int el = r*32 + (cu ^ ((r & 7) << 2));
                float2 p = unpackBf(AO[el], AO[4096 + el]);
                co = fmaf(sAabs[b], (tid & 1) ? p.y : p.x, co);
            }
            v = fmaf(sExp[ci], co, v);
        }
        atomicAdd(&g_numer[tid], v);
    } else if (tid == 64) {
        float se = 0.f, st = 0.f;
        for (int ci = 0; ci < 16; ci++) { se += sExp[ci]; st += sAvg[ci]; }
        atomicAdd(&g_denom, se); atomicAdd(&g_tsum, st);
    }
    const float tenA = sTen[rA], tenB = sTen[rB];

    // gate r
    ZACC(acc8, 8);
    GEMM_STAGED(acc8, 8, AO, 5, 4096, g_Iwih[0], 4096, 5, 32, chalf*64);
    GEMM_STAGED(acc8, 8, AH, 6, 8192, g_Iwhh[0], 8192, 6, 64, chalf*64);
    #pragma unroll
    for (int n = 0; n < 8; n++) {
        int u = chalf*64 + n*8 + 2*t;
        int pA = rA*128 + (u ^ sw), pB = rB*128 + (u ^ sw);
        sRN[pA]     = fsigm(acc8[n][0] + bih[u] + bhh[u] + tenA*Wih[u*65 + 64]);
        sRN[pA + 1] = fsigm(acc8[n][1] + bih[u+1] + bhh[u+1] + tenA*Wih[(u+1)*65 + 64]);
        sRN[pB]     = fsigm(acc8[n][2] + bih[u] + bhh[u] + tenB*Wih[u*65 + 64]);
        sRN[pB + 1] = fsigm(acc8[n][3] + bih[u+1] + bhh[u+1] + tenB*Wih[(u+1)*65 + 64]);
    }

    // gate n (inn from AO@wih2, hn from AH@whh2) -> n in place of r
    float accI[8][4];
    ZACC(accI, 8);
    GEMM_STAGED(accI, 8, AO, 5, 4096, g_Iwih[2], 4096, 5, 32, chalf*64);
    ZACC(acc8, 8);
    GEMM_STAGED(acc8, 8, AH, 6, 8192, g_Iwhh[2], 8192, 6, 64, chalf*64);
    #pragma unroll
    for (int n = 0; n < 8; n++) {
        int u = chalf*64 + n*8 + 2*t;
        int pA = rA*128 + (u ^ sw), pB = rB*128 + (u ^ sw);
        #pragma unroll
        for (int j = 0; j < 2; j++) {
            int uu = 256 + u + j;
            float rrA = sRN[pA + j];
            sRN[pA + j] = ftanh(accI[n][j] + bih[uu] + tenA*Wih[uu*65 + 64]
                                + rrA * (acc8[n][j] + bhh[uu]));
            float rrB = sRN[pB + j];
            sRN[pB + j] = ftanh(accI[n][2+j] + bih[uu] + tenB*Wih[uu*65 + 64]
                                + rrB * (acc8[n][2+j] + bhh[uu]));
        }
    }

    // gate z + combine -> newh (in place)
    ZACC(acc8, 8);
    GEMM_STAGED(acc8, 8, AO, 5, 4096, g_Iwih[1], 4096, 5, 32, chalf*64);
    GEMM_STAGED(acc8, 8, AH, 6, 8192, g_Iwhh[1], 8192, 6, 64, chalf*64);
    #pragma unroll
    for (int n = 0; n < 8; n++) {
        int u = chalf*64 + n*8 + 2*t;
        int cu = u >> 1;
        int pA = rA*128 + (u ^ sw), pB = rB*128 + (u ^ sw);
        int eA = rA*64 + (cu ^ sw), eB = rB*64 + (cu ^ sw);
        float2 hA = unpackBf(AH[eA], AH[8192 + eA]);
        float2 hB = unpackBf(AH[eB], AH[8192 + eB]);
        #pragma unroll
        for (int j = 0; j < 2; j++) {
            int uu = 128 + u + j;
            float zA = fsigm(acc8[n][j] + bih[uu] + bhh[uu] + tenA*Wih[uu*65 + 64]);
            float zB = fsigm(acc8[n][2+j] + bih[uu] + bhh[uu] + tenB*Wih[uu*65 + 64]);
            float hAv = j ? hA.y : hA.x, hBv = j ? hB.y : hB.x;
            sRN[pA + j] = (1.f - zA)*sRN[pA + j] + zA*hAv;
            sRN[pB + j] = (1.f - zB)*sRN[pB + j] + zB*hBv;
        }
    }
    __syncthreads();

    // faction sums + copy-out
    const int f = c0 >> 11;
    const bool deb = (c0 & 2047) < 512;
    for (int idx = tid; idx < 1024; idx += 512) {
        int b = idx >> 7, u = idx & 127;
        float s = 0.f;
        #pragma unroll
        for (int ci = 0; ci < 16; ci++)
            s += sRN[(b*16 + ci)*128 + (u ^ ((ci & 7) << 2))];
        atomicAdd(&g_fsum[(b*8 + f)*HIDD + u], s);
        if (deb) atomicAdd(&g_dsum[(b*8 + f)*HIDD + u], s);
    }
    for (int i = tid; i < 16384; i += 512) {
        int r = i >> 7, k = i & 127;
        out[nh_off + ((long long)((r >> 4)*NCC + c0 + (r & 15)))*HIDD + k]
            = sRN[r*128 + (k ^ ((r & 7) << 2))];
    }
}

// ---------------- Stage C ----------------
__global__ void __launch_bounds__(1024) stageC(
    const float* __restrict__ mixW, const float* __restrict__ mixb,
    const float* __restrict__ headW, const float* __restrict__ headb,
    const int* __restrict__ stepp, float* __restrict__ out, long long nh_off)
{
    __shared__ float sMF[NB*HIDD];
    __shared__ float sC[OUTD];
    int tid = threadIdx.x;
    int lane = tid & 31, warp = tid >> 5;
    int st = *stepp;
    {
        int b = tid >> 7, u = tid & 127;
        float Sf = 0.f, Sd = 0.f;
        for (int f = 0; f < 8; f++) {
            float fsv = g_fsum[(b*8 + f)*HIDD + u];
            float fm = fsv * (1.f/2048.f);
            g_fm[(b*8 + f)*HIDD + u] = fm;
            Sf += fsv;
            Sd += 0.85f * g_dsum[(b*8 + f)*HIDD + u] + 76.8f * fm;
        }
        float m0 = Sf * (1.f/16384.f);
        g_m0[tid] = m0;
        sMF[tid] = (st > 5) ? (m0 + 0.15f * (0.25f*m0 - Sd * (1.f/16384.f))) : m0;
    }
    __syncthreads();
    // interf GEMV: warp per 4 outputs, lanes coalesced over k
    #pragma unroll
    for (int j2 = 0; j2 < 4; j2++) {
        int u = warp * 4 + j2;
        const float* wrow = mixW + u * 1024;
        float s = 0.f;
        #pragma unroll 8
        for (int i = lane; i < 1024; i += 32) s = fmaf(sMF[i], wrow[i], s);
        #pragma unroll
        for (int o = 16; o > 0; o >>= 1) s += __shfl_down_sync(0xFFFFFFFF, s, o);
        if (lane == 0) g_interf[u] = s + mixb[u];
    }
    if (tid >= 256 && tid < 320) sC[tid - 256] = g_numer[tid - 256] / g_denom;
    __syncthreads();
    if (tid < OUTD) {
        float p = headb[tid];
        #pragma unroll
        for (int o = 0; o < OUTD; o++) p = fmaf(sC[o], headW[tid*OUTD + o], p);
        out[tid] = p;
    } else if (tid == 64) {
        out[nh_off - 1] = g_tsum * (1.f/16384.f);
    }
}

// ---------------- Stage D (4 elems/thread) ----------------
__global__ void __launch_bounds__(256) stageD(const int* __restrict__ stepp,
                                              float* __restrict__ out, long long nh_off)
{
    long long base = ((long long)blockIdx.x*256 + threadIdx.x) * 4;
    int u = (int)(base & 127);
    long long rc = base >> 7;
    int c = (int)(rc & (NCC - 1));
    int b = (int)(rc >> 14);
    int f = c >> 11;
    bool dbg = (*stepp > 5) && ((c & 2047) < 512);
    float* p = out + nh_off + base;
    const float* fm = g_fm + (b*8 + f)*HIDD + u;
    const float* m0 = g_m0 + b*HIDD + u;
    const float* itf = g_interf + u;
    #pragma unroll
    for (int j = 0; j < 4; j++) {
        float v = 0.85f*p[j] + 0.15f*fm[j];
        if (dbg) v = 0.85f*v + 0.15f*m0[j];
        if (b == 0) v += 0.05f*itf[j];
        p[j] = v;
    }
}

extern "C" void kernel_launch(void* const* d_in, const int* in_sizes, int n_in,
                              void* d_out, int out_size) {
    const float* x     = (const float*)d_in[0];
    const float* noise = (const float*)d_in[1];
    const float* amps  = (const float*)d_in[2];
    const float* hidd  = (const float*)d_in[3];
    const float* eaW1  = (const float*)d_in[4];
    const float* eaB1  = (const float*)d_in[5];
    const float* eaW2  = (const float*)d_in[6];
    const float* eaB2  = (const float*)d_in[7];
    const float* egW1  = (const float*)d_in[8];
    const float* egB1  = (const float*)d_in[9];
    const float* egW2  = (const float*)d_in[10];
    const float* egB2  = (const float*)d_in[11];
    const float* Wih   = (const float*)d_in[12];
    const float* Whh   = (const float*)d_in[13];
    const float* bih   = (const float*)d_in[14];
    const float* bhh   = (const float*)d_in[15];
    const float* headW = (const float*)d_in[16];
    const float* headb = (const float*)d_in[17];
    const float* mixW  = (const float*)d_in[18];
    const float* mixb  = (const float*)d_in[19];
    const int*   step  = (const int*)d_in[20];
    float* out = (float*)d_out;
    long long nh_off = (long long)out_size - (long long)NB*NCC*HIDD;

    cudaFuncSetAttribute(stageB, cudaFuncAttributeMaxDynamicSharedMemorySize, SMEM_B_BYTES);

    stageA<<<1, 256>>>(x, noise, amps, eaW1, eaB1, egW1, egB1);
    stageA2<<<96, 256>>>(eaW1, egW1, eaW2, egW2, Wih, Whh);
    stageB<<<NCC/16, 512, SMEM_B_BYTES>>>(hidd, Wih, bih, bhh, eaB2, egB2, out, nh_off);
    stageC<<<1, 1024>>>(mixW, mixb, headW, headb, step, out, nh_off);
    stageD<<<(NB*NCC*HIDD)/1024, 256>>>(step, out, nh_off);
}

// round 16
// speedup vs baseline: 2.4637x; 1.0271x over previous
#include <cuda_runtime.h>
#include <cuda_bf16.h>
#include <math.h>
#include <stdint.h>

#define NB 8
#define NCC 16384
#define HIDD 128
#define OUTD 64

typedef unsigned int uint32;

// ---- stage B smem byte offsets (known-good R10/R14 layout) ----
#define AHB 1024
#define AT1B 66560
#define AOB 132096
#define SWB2 164864
#define SMEM_B_BYTES 197632

// ---------------- device scratch ----------------
__device__ float g_ea1b[NB*128];
__device__ float g_eg1b[NB*128];
__device__ float g_aabs[NB];
__device__ float g_fsum[NB*8*HIDD];
__device__ float g_dsum[NB*8*HIDD];
__device__ float g_fm[NB*8*HIDD];
__device__ float g_m0[NB*HIDD];
__device__ float g_interf[HIDD];
__device__ float g_numer[OUTD];
__device__ float g_denom, g_tsum;

// pre-swizzled bf16-pair weight images: hi block then lo block
__device__ __align__(16) uint32 g_Iea1[16384];
__device__ __align__(16) uint32 g_Ieg1[16384];
__device__ __align__(16) uint32 g_Iea2[8192];
__device__ __align__(16) uint32 g_Ieg2[8192];    // negated
__device__ __align__(16) uint32 g_Iwih[3][8192];
__device__ __align__(16) uint32 g_Iwhh[3][16384];

__device__ __forceinline__ void splitPack(float v0, float v1, uint32& hi, uint32& lo) {
    __nv_bfloat16 h0 = __float2bfloat16_rn(v0), h1 = __float2bfloat16_rn(v1);
    hi = (uint32)__bfloat16_as_ushort(h0) | ((uint32)__bfloat16_as_ushort(h1) << 16);
    __nv_bfloat16 l0 = __float2bfloat16_rn(v0 - __bfloat162float(h0));
    __nv_bfloat16 l1 = __float2bfloat16_rn(v1 - __bfloat162float(h1));
    lo = (uint32)__bfloat16_as_ushort(l0) | ((uint32)__bfloat16_as_ushort(l1) << 16);
}
__device__ __forceinline__ float2 unpackBf(uint32 hi, uint32 lo) {
    float a = __bfloat162float(__ushort_as_bfloat16((unsigned short)(hi & 0xFFFF)))
            + __bfloat162float(__ushort_as_bfloat16((unsigned short)(lo & 0xFFFF)));
    float b = __bfloat162float(__ushort_as_bfloat16((unsigned short)(hi >> 16)))
            + __bfloat162float(__ushort_as_bfloat16((unsigned short)(lo >> 16)));
    return make_float2(a, b);
}
__device__ __forceinline__ void mma_bf16(float* c, const uint32* a, uint32 b0, uint32 b1) {
    asm volatile("mma.sync.aligned.m16n8k16.row.col.f32.bf16.bf16.f32 "
        "{%0,%1,%2,%3}, {%4,%5,%6,%7}, {%8,%9}, {%0,%1,%2,%3};"
        : "+f"(c[0]), "+f"(c[1]), "+f"(c[2]), "+f"(c[3])
        : "r"(a[0]), "r"(a[1]), "r"(a[2]), "r"(a[3]), "r"(b0), "r"(b1));
}
__device__ __forceinline__ float fsigm(float x) { return 1.f / (1.f + __expf(-x)); }
__device__ __forceinline__ float ftanh(float x) {
    float y; asm("tanh.approx.f32 %0, %1;" : "=f"(y) : "f"(x)); return y;
}
#define LDSM4(r0, r1, r2, r3, addr) \
    asm volatile("ldmatrix.sync.aligned.m8n8.x4.shared.b16 {%0,%1,%2,%3}, [%4];" \
        : "=r"(r0), "=r"(r1), "=r"(r2), "=r"(r3) : "r"(addr))

// split-bf16 warp GEMM with ldmatrix fragment loads (two-stage staging form).
// hiStage: Ahi*W + Alo*W. loStage(false): Ahi*W (W = lo image staged).
__device__ __forceinline__ void wgemm(float (*acc)[4], int nT,
    const uint32* A, int saSh, int aLo, const uint32* W, int swSh,
    int k2, int r0, int lid, int nbase, bool hiStage)
{
    const int sub = lid >> 3, rr = lid & 7;
    const int arow = r0 + ((sub & 1) << 3) + rr;      // A lane row
    const int apo = (sub >> 1) << 2;                  // A pair offset 0/4
    const int arsw = (arow & 7) << 2;
    const int wro = ((sub >> 1) << 3) + rr;           // W lane row within 16-group
    const int wpo = (sub & 1) << 2;                   // W pair offset 0/4
    const int wrsw = (rr & 7) << 2;                   // (wrow&7)==rr
    for (int kk = 0; kk < k2; kk += 8) {
        uint32 ah[4], al[4];
        uint32 aAddr = (uint32)__cvta_generic_to_shared(
            A + (arow << saSh) + ((kk + apo) ^ arsw));
        LDSM4(ah[0], ah[1], ah[2], ah[3], aAddr);
        if (hiStage) {
            uint32 aAddrL = (uint32)__cvta_generic_to_shared(
                A + aLo + (arow << saSh) + ((kk + apo) ^ arsw));
            LDSM4(al[0], al[1], al[2], al[3], aAddrL);
        }
        #pragma unroll
        for (int p = 0; p < 4; p++) {
            if (2*p >= nT) break;
            int wrow = nbase + (p << 4) + wro;
            uint32 wAddr = (uint32)__cvta_generic_to_shared(
                W + (wrow << swSh) + ((kk + wpo) ^ wrsw));
            uint32 b0, b1, b2, b3;
            LDSM4(b0, b1, b2, b3, wAddr);
            mma_bf16(acc[2*p], ah, b0, b1);
            mma_bf16(acc[2*p + 1], ah, b2, b3);
            if (hiStage) {
                mma_bf16(acc[2*p], al, b0, b1);
                mma_bf16(acc[2*p + 1], al, b2, b3);
            }
        }
    }
}

// ---------------- Stage A ----------------
__global__ void __launch_bounds__(256) stageA(
    const float* __restrict__ x, const float* __restrict__ noise,
    const float* __restrict__ amps,
    const float* __restrict__ eaW1, const float* __restrict__ eaB1,
    const float* __restrict__ egW1, const float* __restrict__ egB1)
{
    __shared__ float sXB[NB*64];
    int tid = threadIdx.x;
    for (int i = tid; i < NB*8*HIDD; i += 256) { g_fsum[i] = 0.f; g_dsum[i] = 0.f; }
    if (tid < OUTD) g_numer[tid] = 0.f;
    if (tid == 0) {
        g_denom = 0.f; g_tsum = 0.f;
        float s = 1e-8f, t[NB];
        for (int b = 0; b < NB; b++) { t[b] = fabsf(amps[b]); s += t[b]; }
        for (int b = 0; b < NB; b++) g_aabs[b] = t[b] / s;
    }
    for (int i = tid; i < NB*64; i += 256) {
        int b = i >> 6, k = i & 63;
        sXB[i] = x[k] + noise[i] * 0.05f * (float)(b + 1);
    }
    __syncthreads();
    for (int i = tid; i < NB*128; i += 256) {
        int b = i >> 7, j = i & 127;
        float s1 = eaB1[j], s2 = egB1[j];
        const float* xb = sXB + b*64;
        #pragma unroll 8
        for (int k = 0; k < 64; k++) {
            s1 = fmaf(xb[k], eaW1[j*192 + k], s1);
            s2 = fmaf(xb[k], egW1[j*192 + k], s2);
        }
        g_ea1b[i] = s1; g_eg1b[i] = s2;
    }
}

// ---------------- Stage A2: pre-swizzled pair-packed images ----------------
__global__ void __launch_bounds__(256) stageA2(
    const float* __restrict__ eaW1, const float* __restrict__ egW1,
    const float* __restrict__ eaW2, const float* __restrict__ egW2,
    const float* __restrict__ Wih,  const float* __restrict__ Whh)
{
    int gt = blockIdx.x*256 + threadIdx.x, gs = gridDim.x*256;
    uint32 hi, lo;
    for (int i = gt; i < 8192; i += gs) {
        int j = i >> 6, cu = i & 63, k = 2*cu;
        int el = j*64 + (cu ^ ((j & 7) << 2));
        splitPack(eaW1[j*192 + 64 + k], eaW1[j*192 + 64 + k + 1], hi, lo);
        g_Iea1[el] = hi; g_Iea1[8192 + el] = lo;
        splitPack(egW1[j*192 + 64 + k], egW1[j*192 + 64 + k + 1], hi, lo);
        g_Ieg1[el] = hi; g_Ieg1[8192 + el] = lo;
    }
    for (int i = gt; i < 4096; i += gs) {
        int j = i >> 6, cu = i & 63, k = 2*cu;
        int el = j*64 + (cu ^ ((j & 7) << 2));
        splitPack(eaW2[j*128 + k], eaW2[j*128 + k + 1], hi, lo);
        g_Iea2[el] = hi; g_Iea2[4096 + el] = lo;
        splitPack(-egW2[j*128 + k], -egW2[j*128 + k + 1], hi, lo);
        g_Ieg2[el] = hi; g_Ieg2[4096 + el] = lo;
    }
    for (int gg = 0; gg < 3; gg++) {
        for (int i = gt; i < 4096; i += gs) {
            int j = i >> 5, cu = i & 31, k = 2*cu;
            int el = j*32 + (cu ^ ((j & 7) << 2));
            splitPack(Wih[(gg*128 + j)*65 + k], Wih[(gg*128 + j)*65 + k + 1], hi, lo);
            g_Iwih[gg][el] = hi; g_Iwih[gg][4096 + el] = lo;
        }
        for (int i = gt; i < 8192; i += gs) {
            int j = i >> 6, cu = i & 63, k = 2*cu;
            int el = j*64 + (cu ^ ((j & 7) << 2));
            splitPack(Whh[(gg*128 + j)*128 + k], Whh[(gg*128 + j)*128 + k + 1], hi, lo);
            g_Iwhh[gg][el] = hi; g_Iwhh[gg][8192 + el] = lo;
        }
    }
}

// ---------------- Stage B ----------------
__global__ void __launch_bounds__(512, 1) stageB(
    const float* __restrict__ hiddens, const float* __restrict__ Wih,
    const float* __restrict__ bih, const float* __restrict__ bhh,
    const float* __restrict__ eaB2, const float* __restrict__ egB2,
    float* __restrict__ out, long long nh_off)
{
    extern __shared__ char smem[];
    const int tid = threadIdx.x, wid = tid >> 5, lid = tid & 31;
    const int g = lid >> 2, t = lid & 3;
    const int rt = wid >> 1, chalf = wid & 1, r0 = rt * 16;
    const int c0 = blockIdx.x * 16;
    const int sw = g << 2;

    float* sTen = (float*)(smem);
    float* sAvg = (float*)(smem + 512);
    float* sExp = (float*)(smem + 576);
    float* sAabs = (float*)(smem + 640);
    uint32* AH  = (uint32*)(smem + AHB);
    uint32* AT1 = (uint32*)(smem + AT1B);
    uint32* AO  = (uint32*)(smem + AOB);
    uint32* SW  = (uint32*)(smem + SWB2);
    float*  sRN = (float*)(smem + AT1B);   // overlays AT1 after last AT1 use

    if (tid < 8) sAabs[tid] = g_aabs[tid];

    // build AH pair tile (128 rows x 64 k-pairs, swizzled)
    for (int i = tid; i < 8192; i += 512) {
        int r = i >> 6, cu = i & 63;
        const float* hp = hiddens + ((long long)((r >> 4)*NCC + c0 + (r & 15)))*HIDD + 2*cu;
        uint32 hi, lo; splitPack(hp[0], hp[1], hi, lo);
        int el = r*64 + (cu ^ ((r & 7) << 2));
        AH[el] = hi; AH[8192 + el] = lo;
    }

#define GEMM_STAGED(acc, nT, Abuf, saSh, aLo, img, nWords, swSh, k2, nbase) { \
    __syncthreads(); \
    { const float4* _s = (const float4*)(img); float4* _d = (float4*)SW; \
      for (int _i = tid; _i*4 < (nWords); _i += 512) _d[_i] = _s[_i]; } \
    __syncthreads(); \
    wgemm(acc, nT, Abuf, saSh, aLo, SW, swSh, k2, r0, lid, nbase, true); \
    __syncthreads(); \
    { const float4* _s = (const float4*)((img) + (nWords)); float4* _d = (float4*)SW; \
      for (int _i = tid; _i*4 < (nWords); _i += 512) _d[_i] = _s[_i]; } \
    __syncthreads(); \
    wgemm(acc, nT, Abuf, saSh, aLo, SW, swSh, k2, r0, lid, nbase, false); \
}
#define ZACC(a, n) { _Pragma("unroll") for (int _n = 0; _n < (n); _n++) { (a)[_n][0]=0;(a)[_n][1]=0;(a)[_n][2]=0;(a)[_n][3]=0; } }

    float acc8[8][4], accA[4][4], accG[4][4];
    const int rA = r0 + g, rB = r0 + 8 + g;

    // P1: t1a = relu(H @ eaW1h^T + biasA)
    ZACC(acc8, 8);
    GEMM_STAGED(acc8, 8, AH, 6, 8192, g_Iea1, 8192, 6, 64, chalf*64);
    #pragma unroll
    for (int n = 0; n < 8; n++) {
        int col = chalf*64 + n*8 + 2*t;
        float b0 = g_ea1b[rt*128 + col], b1 = g_ea1b[rt*128 + col + 1];
        float v0 = fmaxf(acc8[n][0] + b0, 0.f), v1 = fmaxf(acc8[n][1] + b1, 0.f);
        float v2 = fmaxf(acc8[n][2] + b0, 0.f), v3 = fmaxf(acc8[n][3] + b1, 0.f);
        int cu = col >> 1;
        int elA = rA*64 + (cu ^ sw), elB = rB*64 + (cu ^ sw);
        uint32 hi, lo;
        splitPack(v0, v1, hi, lo); AT1[elA] = hi; AT1[8192 + elA] = lo;
        splitPack(v2, v3, hi, lo); AT1[elB] = hi; AT1[8192 + elB] = lo;
    }

    // P2: a = t1a @ eaW2^T (raw, biases added in P4)
    ZACC(accA, 4);
    GEMM_STAGED(accA, 4, AT1, 6, 8192, g_Iea2, 4096, 6, 64, chalf*32);

    // P3: t1g
    ZACC(acc8, 8);
    GEMM_STAGED(acc8, 8, AH, 6, 8192, g_Ieg1, 8192, 6, 64, chalf*64);
    #pragma unroll
    for (int n = 0; n < 8; n++) {
        int col = chalf*64 + n*8 + 2*t;
        float b0 = g_eg1b[rt*128 + col], b1 = g_eg1b[rt*128 + col + 1];
        float v0 = fmaxf(acc8[n][0] + b0, 0.f), v1 = fmaxf(acc8[n][1] + b1, 0.f);
        float v2 = fmaxf(acc8[n][2] + b0, 0.f), v3 = fmaxf(acc8[n][3] + b1, 0.f);
        int cu = col >> 1;
        int elA = rA*64 + (cu ^ sw), elB = rB*64 + (cu ^ sw);
        uint32 hi, lo;
        splitPack(v0, v1, hi, lo); AT1[elA] = hi; AT1[8192 + elA] = lo;
        splitPack(v2, v3, hi, lo); AT1[elB] = hi; AT1[8192 + elB] = lo;
    }

    // P4: out = a - g  (eg2 image pre-negated)
    ZACC(accG, 4);
    GEMM_STAGED(accG, 4, AT1, 6, 8192, g_Ieg2, 4096, 6, 64, chalf*32);
    #pragma unroll
    for (int n = 0; n < 4; n++) {
        int col = chalf*32 + n*8 + 2*t;
        float e0 = eaB2[col] - egB2[col], e1 = eaB2[col+1] - egB2[col+1];
        float o0 = accA[n][0] + accG[n][0] + e0, o1 = accA[n][1] + accG[n][1] + e1;
        float o2 = accA[n][2] + accG[n][2] + e0, o3 = accA[n][3] + accG[n][3] + e1;
        int cu = col >> 1;
        int elA = rA*32 + (cu ^ sw), elB = rB*32 + (cu ^ sw);
        uint32 hi, lo;
        splitPack(o0, o1, hi, lo); AO[elA] = hi; AO[4096 + elA] = lo;
        splitPack(o2, o3, hi, lo); AO[elB] = hi; AO[4096 + elB] = lo;
    }
    __syncthreads();

    // tension per row
    if (tid < 128) {
        int row = tid; float s = 0.f;
        int rsw = (row & 7) << 2;
        #pragma unroll 8
        for (int cu = 0; cu < 32; cu++) {
            int el = row*32 + (cu ^ rsw);
            float2 p = unpackBf(AO[el], AO[4096 + el]);
            s = fmaf(p.x, p.x, s); s = fmaf(p.y, p.y, s);
        }
        sTen[row] = s * (1.f/64.f);
    }
    __syncthreads();
    if (tid < 16) {
        float s = 0.f;
        #pragma unroll
        for (int b = 0; b < 8; b++) s += sTen[b*16 + tid];
        float avg = s * 0.125f;
        sAvg[tid] = avg; sExp[tid] = __expf(avg);
    }
    __syncthreads();
    if (tid < 64) {
        int cu = tid >> 1; float v = 0.f;
        for (int ci = 0; ci < 16; ci++) {
            float co = 0.f;
            #pragma unroll
            for (int b = 0; b < 8; b++) {
                int r = b*16 + ci;
                int el = r*32 + (cu ^ ((r & 7) << 2));
                float2 p = unpackBf(AO[el], AO[4096 + el]);
                co = fmaf(sAabs[b], (tid & 1) ? p.y : p.x, co);
            }
            v = fmaf(sExp[ci], co, v);
        }
        atomicAdd(&g_numer[tid], v);
    } else if (tid == 64) {
        float se = 0.f, st = 0.f;
        for (int ci = 0; ci < 16; ci++) { se += sExp[ci]; st += sAvg[ci]; }
        atomicAdd(&g_denom, se); atomicAdd(&g_tsum, st);
    }
    const float tenA = sTen[rA], tenB = sTen[rB];

    // gate r
    ZACC(acc8, 8);
    GEMM_STAGED(acc8, 8, AO, 5, 4096, g_Iwih[0], 4096, 5, 32, chalf*64);
    GEMM_STAGED(acc8, 8, AH, 6, 8192, g_Iwhh[0], 8192, 6, 64, chalf*64);
    #pragma unroll
    for (int n = 0; n < 8; n++) {
        int u = chalf*64 + n*8 + 2*t;
        int pA = rA*128 + (u ^ sw), pB = rB*128 + (u ^ sw);
        sRN[pA]     = fsigm(acc8[n][0] + bih[u] + bhh[u] + tenA*Wih[u*65 + 64]);
        sRN[pA + 1] = fsigm(acc8[n][1] + bih[u+1] + bhh[u+1] + tenA*Wih[(u+1)*65 + 64]);
        sRN[pB]     = fsigm(acc8[n][2] + bih[u] + bhh[u] + tenB*Wih[u*65 + 64]);
        sRN[pB + 1] = fsigm(acc8[n][3] + bih[u+1] + bhh[u+1] + tenB*Wih[(u+1)*65 + 64]);
    }

    // gate n (inn from AO@wih2, hn from AH@whh2) -> n in place of r
    float accI[8][4];
    ZACC(accI, 8);
    GEMM_STAGED(accI, 8, AO, 5, 4096, g_Iwih[2], 4096, 5, 32, chalf*64);
    ZACC(acc8, 8);
    GEMM_STAGED(acc8, 8, AH, 6, 8192, g_Iwhh[2], 8192, 6, 64, chalf*64);
    #pragma unroll
    for (int n = 0; n < 8; n++) {
        int u = chalf*64 + n*8 + 2*t;
        int pA = rA*128 + (u ^ sw), pB = rB*128 + (u ^ sw);
        #pragma unroll
        for (int j = 0; j < 2; j++) {
            int uu = 256 + u + j;
            float rrA = sRN[pA + j];
            sRN[pA + j] = ftanh(accI[n][j] + bih[uu] + tenA*Wih[uu*65 + 64]
                                + rrA * (acc8[n][j] + bhh[uu]));
            float rrB = sRN[pB + j];
            sRN[pB + j] = ftanh(accI[n][2+j] + bih[uu] + tenB*Wih[uu*65 + 64]
                                + rrB * (acc8[n][2+j] + bhh[uu]));
        }
    }

    // gate z + combine -> newh (in place)
    ZACC(acc8, 8);
    GEMM_STAGED(acc8, 8, AO, 5, 4096, g_Iwih[1], 4096, 5, 32, chalf*64);
    GEMM_STAGED(acc8, 8, AH, 6, 8192, g_Iwhh[1], 8192, 6, 64, chalf*64);
    #pragma unroll
    for (int n = 0; n < 8; n++) {
        int u = chalf*64 + n*8 + 2*t;
        int cu = u >> 1;
        int pA = rA*128 + (u ^ sw), pB = rB*128 + (u ^ sw);
        int eA = rA*64 + (cu ^ sw), eB = rB*64 + (cu ^ sw);
        float2 hA = unpackBf(AH[eA], AH[8192 + eA]);
        float2 hB = unpackBf(AH[eB], AH[8192 + eB]);
        #pragma unroll
        for (int j = 0; j < 2; j++) {
            int uu = 128 + u + j;
            float zA = fsigm(acc8[n][j] + bih[uu] + bhh[uu] + tenA*Wih[uu*65 + 64]);
            float zB = fsigm(acc8[n][2+j] + bih[uu] + bhh[uu] + tenB*Wih[uu*65 + 64]);
            float hAv = j ? hA.y : hA.x, hBv = j ? hB.y : hB.x;
            sRN[pA + j] = (1.f - zA)*sRN[pA + j] + zA*hAv;
            sRN[pB + j] = (1.f - zB)*sRN[pB + j] + zB*hBv;
        }
    }
    __syncthreads();

    // faction sums + copy-out
    const int f = c0 >> 11;
    const bool deb = (c0 & 2047) < 512;
    for (int idx = tid; idx < 1024; idx += 512) {
        int b = idx >> 7, u = idx & 127;
        float s = 0.f;
        #pragma unroll
        for (int ci = 0; ci < 16; ci++)
            s += sRN[(b*16 + ci)*128 + (u ^ ((ci & 7) << 2))];
        atomicAdd(&g_fsum[(b*8 + f)*HIDD + u], s);
        if (deb) atomicAdd(&g_dsum[(b*8 + f)*HIDD + u], s);
    }
    for (int i = tid; i < 16384; i += 512) {
        int r = i >> 7, k = i & 127;
        out[nh_off + ((long long)((r >> 4)*NCC + c0 + (r & 15)))*HIDD + k]
            = sRN[r*128 + (k ^ ((r & 7) << 2))];
    }
}

// ---------------- Stage C ----------------
__global__ void __launch_bounds__(1024) stageC(
    const float* __restrict__ mixW, const float* __restrict__ mixb,
    const float* __restrict__ headW, const float* __restrict__ headb,
    const int* __restrict__ stepp, float* __restrict__ out, long long nh_off)
{
    __shared__ float sMF[NB*HIDD];
    __shared__ float sC[OUTD];
    int tid = threadIdx.x;
    int lane = tid & 31, warp = tid >> 5;
    int st = *stepp;
    {
        int b = tid >> 7, u = tid & 127;
        float Sf = 0.f, Sd = 0.f;
        for (int f = 0; f < 8; f++) {
            float fsv = g_fsum[(b*8 + f)*HIDD + u];
            float fm = fsv * (1.f/2048.f);
            g_fm[(b*8 + f)*HIDD + u] = fm;
            Sf += fsv;
            Sd += 0.85f * g_dsum[(b*8 + f)*HIDD + u] + 76.8f * fm;
        }
        float m0 = Sf * (1.f/16384.f);
        g_m0[tid] = m0;
        sMF[tid] = (st > 5) ? (m0 + 0.15f * (0.25f*m0 - Sd * (1.f/16384.f))) : m0;
    }
    __syncthreads();
    // interf GEMV: warp per 4 outputs, lanes coalesced over k
    #pragma unroll
    for (int j2 = 0; j2 < 4; j2++) {
        int u = warp * 4 + j2;
        const float* wrow = mixW + u * 1024;
        float s = 0.f;
        #pragma unroll 8
        for (int i = lane; i < 1024; i += 32) s = fmaf(sMF[i], wrow[i], s);
        #pragma unroll
        for (int o = 16; o > 0; o >>= 1) s += __shfl_down_sync(0xFFFFFFFF, s, o);
        if (lane == 0) g_interf[u] = s + mixb[u];
    }
    if (tid >= 256 && tid < 320) sC[tid - 256] = g_numer[tid - 256] / g_denom;
    __syncthreads();
    if (tid < OUTD) {
        float p = headb[tid];
        #pragma unroll
        for (int o = 0; o < OUTD; o++) p = fmaf(sC[o], headW[tid*OUTD + o], p);
        out[tid] = p;
    } else if (tid == 64) {
        out[nh_off - 1] = g_tsum * (1.f/16384.f);
    }
}

// ---------------- Stage D (4 elems/thread) ----------------
__global__ void __launch_bounds__(256) stageD(const int* __restrict__ stepp,
                                              float* __restrict__ out, long long nh_off)
{
    long long base = ((long long)blockIdx.x*256 + threadIdx.x) * 4;
    int u = (int)(base & 127);
    long long rc = base >> 7;
    int c = (int)(rc & (NCC - 1));
    int b = (int)(rc >> 14);
    int f = c >> 11;
    bool dbg = (*stepp > 5) && ((c & 2047) < 512);
    float* p = out + nh_off + base;
    const float* fm = g_fm + (b*8 + f)*HIDD + u;
    const float* m0 = g_m0 + b*HIDD + u;
    const float* itf = g_interf + u;
    #pragma unroll
    for (int j = 0; j < 4; j++) {
        float v = 0.85f*p[j] + 0.15f*fm[j];
        if (dbg) v = 0.85f*v + 0.15f*m0[j];
        if (b == 0) v += 0.05f*itf[j];
        p[j] = v;
    }
}

extern "C" void kernel_launch(void* const* d_in, const int* in_sizes, int n_in,
                              void* d_out, int out_size) {
    const float* x     = (const float*)d_in[0];
    const float* noise = (const float*)d_in[1];
    const float* amps  = (const float*)d_in[2];
    const float* hidd  = (const float*)d_in[3];
    const float* eaW1  = (const float*)d_in[4];
    const float* eaB1  = (const float*)d_in[5];
    const float* eaW2  = (const float*)d_in[6];
    const float* eaB2  = (const float*)d_in[7];
    const float* egW1  = (const float*)d_in[8];
    const float* egB1  = (const float*)d_in[9];
    const float* egW2  = (const float*)d_in[10];
    const float* egB2  = (const float*)d_in[11];
    const float* Wih   = (const float*)d_in[12];
    const float* Whh   = (const float*)d_in[13];
    const float* bih   = (const float*)d_in[14];
    const float* bhh   = (const float*)d_in[15];
    const float* headW = (const float*)d_in[16];
    const float* headb = (const float*)d_in[17];
    const float* mixW  = (const float*)d_in[18];
    const float* mixb  = (const float*)d_in[19];
    const int*   step  = (const int*)d_in[20];
    float* out = (float*)d_out;
    long long nh_off = (long long)out_size - (long long)NB*NCC*HIDD;

    cudaFuncSetAttribute(stageB, cudaFuncAttributeMaxDynamicSharedMemorySize, SMEM_B_BYTES);

    stageA<<<1, 256>>>(x, noise, amps, eaW1, eaB1, egW1, egB1);
    stageA2<<<96, 256>>>(eaW1, egW1, eaW2, egW2, Wih, Whh);
    stageB<<<NCC/16, 512, SMEM_B_BYTES>>>(hidd, Wih, bih, bhh, eaB2, egB2, out, nh_off);
    stageC<<<1, 1024>>>(mixW, mixb, headW, headb, step, out, nh_off);
    stageD<<<(NB*NCC*HIDD)/1024, 256>>>(step, out, nh_off);
}

// round 17
// speedup vs baseline: 2.6223x; 1.0644x over previous
#include <cuda_runtime.h>
#include <cuda_bf16.h>
#include <math.h>
#include <stdint.h>

#define NB 8
#define NCC 16384
#define HIDD 128
#define OUTD 64

typedef unsigned int uint32;

// ---- stage B smem byte offsets (known-good R10/R14 layout) ----
#define AHB 1024
#define AT1B 66560
#define AOB 132096
#define SWB2 164864
#define SMEM_B_BYTES 197632

// ---------------- device scratch ----------------
__device__ float g_ea1b[NB*128];
__device__ float g_eg1b[NB*128];
__device__ float g_aabs[NB];
__device__ float g_fsum[NB*8*HIDD];
__device__ float g_dsum[NB*8*HIDD];
__device__ float g_fm[NB*8*HIDD];
__device__ float g_m0[NB*HIDD];
__device__ float g_interf[HIDD];
__device__ float g_numer[OUTD];
__device__ float g_denom, g_tsum;

// pre-swizzled bf16-pair weight images: hi block then lo block
__device__ __align__(16) uint32 g_Iea1[16384];
__device__ __align__(16) uint32 g_Ieg1[16384];
__device__ __align__(16) uint32 g_Iea2[8192];
__device__ __align__(16) uint32 g_Ieg2[8192];    // negated
__device__ __align__(16) uint32 g_Iwih[3][8192];
__device__ __align__(16) uint32 g_Iwhh[3][16384];

__device__ __forceinline__ void splitPack(float v0, float v1, uint32& hi, uint32& lo) {
    __nv_bfloat16 h0 = __float2bfloat16_rn(v0), h1 = __float2bfloat16_rn(v1);
    hi = (uint32)__bfloat16_as_ushort(h0) | ((uint32)__bfloat16_as_ushort(h1) << 16);
    __nv_bfloat16 l0 = __float2bfloat16_rn(v0 - __bfloat162float(h0));
    __nv_bfloat16 l1 = __float2bfloat16_rn(v1 - __bfloat162float(h1));
    lo = (uint32)__bfloat16_as_ushort(l0) | ((uint32)__bfloat16_as_ushort(l1) << 16);
}
__device__ __forceinline__ float2 unpackBf(uint32 hi, uint32 lo) {
    float a = __bfloat162float(__ushort_as_bfloat16((unsigned short)(hi & 0xFFFF)))
            + __bfloat162float(__ushort_as_bfloat16((unsigned short)(lo & 0xFFFF)));
    float b = __bfloat162float(__ushort_as_bfloat16((unsigned short)(hi >> 16)))
            + __bfloat162float(__ushort_as_bfloat16((unsigned short)(lo >> 16)));
    return make_float2(a, b);
}
__device__ __forceinline__ void mma_bf16(float* c, const uint32* a, uint32 b0, uint32 b1) {
    asm volatile("mma.sync.aligned.m16n8k16.row.col.f32.bf16.bf16.f32 "
        "{%0,%1,%2,%3}, {%4,%5,%6,%7}, {%8,%9}, {%0,%1,%2,%3};"
        : "+f"(c[0]), "+f"(c[1]), "+f"(c[2]), "+f"(c[3])
        : "r"(a[0]), "r"(a[1]), "r"(a[2]), "r"(a[3]), "r"(b0), "r"(b1));
}
__device__ __forceinline__ float fsigm(float x) { return 1.f / (1.f + __expf(-x)); }
__device__ __forceinline__ float ftanh(float x) {
    float y; asm("tanh.approx.f32 %0, %1;" : "=f"(y) : "f"(x)); return y;
}
#define LDSM4(r0, r1, r2, r3, addr) \
    asm volatile("ldmatrix.sync.aligned.m8n8.x4.shared.b16 {%0,%1,%2,%3}, [%4];" \
        : "=r"(r0), "=r"(r1), "=r"(r2), "=r"(r3) : "r"(addr))

// split-bf16 warp GEMM with ldmatrix fragment loads; warp covers 16 rows x 32 cols.
// hiStage: Ahi*W + Alo*W. loStage(false): Ahi*W (W = lo image staged).
__device__ __forceinline__ void wgemm(float (*acc)[4],
    const uint32* A, int saSh, int aLo, const uint32* W, int swSh,
    int k2, int r0, int lid, int nbase, bool hiStage)
{
    const int sub = lid >> 3, rr = lid & 7;
    const int arow = r0 + ((sub & 1) << 3) + rr;
    const int apo = (sub >> 1) << 2;
    const int arsw = (arow & 7) << 2;
    const int wro = ((sub >> 1) << 3) + rr;
    const int wpo = (sub & 1) << 2;
    const int wrsw = (rr & 7) << 2;
    for (int kk = 0; kk < k2; kk += 8) {
        uint32 ah[4], al[4];
        uint32 aAddr = (uint32)__cvta_generic_to_shared(
            A + (arow << saSh) + ((kk + apo) ^ arsw));
        LDSM4(ah[0], ah[1], ah[2], ah[3], aAddr);
        if (hiStage) {
            uint32 aAddrL = (uint32)__cvta_generic_to_shared(
                A + aLo + (arow << saSh) + ((kk + apo) ^ arsw));
            LDSM4(al[0], al[1], al[2], al[3], aAddrL);
        }
        #pragma unroll
        for (int p = 0; p < 2; p++) {
            int wrow = nbase + (p << 4) + wro;
            uint32 wAddr = (uint32)__cvta_generic_to_shared(
                W + (wrow << swSh) + ((kk + wpo) ^ wrsw));
            uint32 b0, b1, b2, b3;
            LDSM4(b0, b1, b2, b3, wAddr);
            mma_bf16(acc[2*p], ah, b0, b1);
            mma_bf16(acc[2*p + 1], ah, b2, b3);
            if (hiStage) {
                mma_bf16(acc[2*p], al, b0, b1);
                mma_bf16(acc[2*p + 1], al, b2, b3);
            }
        }
    }
}

// ---------------- Stage A ----------------
__global__ void __launch_bounds__(256) stageA(
    const float* __restrict__ x, const float* __restrict__ noise,
    const float* __restrict__ amps,
    const float* __restrict__ eaW1, const float* __restrict__ eaB1,
    const float* __restrict__ egW1, const float* __restrict__ egB1)
{
    __shared__ float sXB[NB*64];
    int tid = threadIdx.x;
    for (int i = tid; i < NB*8*HIDD; i += 256) { g_fsum[i] = 0.f; g_dsum[i] = 0.f; }
    if (tid < OUTD) g_numer[tid] = 0.f;
    if (tid == 0) {
        g_denom = 0.f; g_tsum = 0.f;
        float s = 1e-8f, t[NB];
        for (int b = 0; b < NB; b++) { t[b] = fabsf(amps[b]); s += t[b]; }
        for (int b = 0; b < NB; b++) g_aabs[b] = t[b] / s;
    }
    for (int i = tid; i < NB*64; i += 256) {
        int b = i >> 6, k = i & 63;
        sXB[i] = x[k] + noise[i] * 0.05f * (float)(b + 1);
    }
    __syncthreads();
    for (int i = tid; i < NB*128; i += 256) {
        int b = i >> 7, j = i & 127;
        float s1 = eaB1[j], s2 = egB1[j];
        const float* xb = sXB + b*64;
        #pragma unroll 8
        for (int k = 0; k < 64; k++) {
            s1 = fmaf(xb[k], eaW1[j*192 + k], s1);
            s2 = fmaf(xb[k], egW1[j*192 + k], s2);
        }
        g_ea1b[i] = s1; g_eg1b[i] = s2;
    }
}

// ---------------- Stage A2: pre-swizzled pair-packed images ----------------
__global__ void __launch_bounds__(256) stageA2(
    const float* __restrict__ eaW1, const float* __restrict__ egW1,
    const float* __restrict__ eaW2, const float* __restrict__ egW2,
    const float* __restrict__ Wih,  const float* __restrict__ Whh)
{
    int gt = blockIdx.x*256 + threadIdx.x, gs = gridDim.x*256;
    uint32 hi, lo;
    for (int i = gt; i < 8192; i += gs) {
        int j = i >> 6, cu = i & 63, k = 2*cu;
        int el = j*64 + (cu ^ ((j & 7) << 2));
        splitPack(eaW1[j*192 + 64 + k], eaW1[j*192 + 64 + k + 1], hi, lo);
        g_Iea1[el] = hi; g_Iea1[8192 + el] = lo;
        splitPack(egW1[j*192 + 64 + k], egW1[j*192 + 64 + k + 1], hi, lo);
        g_Ieg1[el] = hi; g_Ieg1[8192 + el] = lo;
    }
    for (int i = gt; i < 4096; i += gs) {
        int j = i >> 6, cu = i & 63, k = 2*cu;
        int el = j*64 + (cu ^ ((j & 7) << 2));
        splitPack(eaW2[j*128 + k], eaW2[j*128 + k + 1], hi, lo);
        g_Iea2[el] = hi; g_Iea2[4096 + el] = lo;
        splitPack(-egW2[j*128 + k], -egW2[j*128 + k + 1], hi, lo);
        g_Ieg2[el] = hi; g_Ieg2[4096 + el] = lo;
    }
    for (int gg = 0; gg < 3; gg++) {
        for (int i = gt; i < 4096; i += gs) {
            int j = i >> 5, cu = i & 31, k = 2*cu;
            int el = j*32 + (cu ^ ((j & 7) << 2));
            splitPack(Wih[(gg*128 + j)*65 + k], Wih[(gg*128 + j)*65 + k + 1], hi, lo);
            g_Iwih[gg][el] = hi; g_Iwih[gg][4096 + el] = lo;
        }
        for (int i = gt; i < 8192; i += gs) {
            int j = i >> 6, cu = i & 63, k = 2*cu;
            int el = j*64 + (cu ^ ((j & 7) << 2));
            splitPack(Whh[(gg*128 + j)*128 + k], Whh[(gg*128 + j)*128 + k + 1], hi, lo);
            g_Iwhh[gg][el] = hi; g_Iwhh[gg][8192 + el] = lo;
        }
    }
}

// ---------------- Stage B (1024 threads, 32 warps) ----------------
__global__ void __launch_bounds__(1024, 1) stageB(
    const float* __restrict__ hiddens, const float* __restrict__ Wih,
    const float* __restrict__ bih, const float* __restrict__ bhh,
    const float* __restrict__ eaB2, const float* __restrict__ egB2,
    float* __restrict__ out, long long nh_off)
{
    extern __shared__ char smem[];
    const int tid = threadIdx.x, wid = tid >> 5, lid = tid & 31;
    const int g = lid >> 2, t = lid & 3;
    const int rt = wid >> 2, cq = wid & 3, r0 = rt * 16;
    const int c0 = blockIdx.x * 16;
    const int sw = g << 2;

    float* sTen = (float*)(smem);
    float* sAvg = (float*)(smem + 512);
    float* sExp = (float*)(smem + 576);
    float* sAabs = (float*)(smem + 640);
    uint32* AH  = (uint32*)(smem + AHB);
    uint32* AT1 = (uint32*)(smem + AT1B);
    uint32* AO  = (uint32*)(smem + AOB);
    uint32* SW  = (uint32*)(smem + SWB2);
    float*  sRN = (float*)(smem + AT1B);   // overlays AT1 after last AT1 use

    if (tid < 8) sAabs[tid] = g_aabs[tid];

    // build AH pair tile (128 rows x 64 k-pairs, swizzled)
    for (int i = tid; i < 8192; i += 1024) {
        int r = i >> 6, cu = i & 63;
        const float* hp = hiddens + ((long long)((r >> 4)*NCC + c0 + (r & 15)))*HIDD + 2*cu;
        uint32 hi, lo; splitPack(hp[0], hp[1], hi, lo);
        int el = r*64 + (cu ^ ((r & 7) << 2));
        AH[el] = hi; AH[8192 + el] = lo;
    }

#define GEMM_STAGED(acc, pred, Abuf, saSh, aLo, img, nWords, swSh, k2, nbase) { \
    __syncthreads(); \
    { const float4* _s = (const float4*)(img); float4* _d = (float4*)SW; \
      for (int _i = tid; _i*4 < (nWords); _i += 1024) _d[_i] = _s[_i]; } \
    __syncthreads(); \
    if (pred) wgemm(acc, Abuf, saSh, aLo, SW, swSh, k2, r0, lid, nbase, true); \
    __syncthreads(); \
    { const float4* _s = (const float4*)((img) + (nWords)); float4* _d = (float4*)SW; \
      for (int _i = tid; _i*4 < (nWords); _i += 1024) _d[_i] = _s[_i]; } \
    __syncthreads(); \
    if (pred) wgemm(acc, Abuf, saSh, aLo, SW, swSh, k2, r0, lid, nbase, false); \
}
#define ZACC(a) { _Pragma("unroll") for (int _n = 0; _n < 4; _n++) { (a)[_n][0]=0;(a)[_n][1]=0;(a)[_n][2]=0;(a)[_n][3]=0; } }

    float acc[4][4], accA[4][4];
    const int rA = r0 + g, rB = r0 + 8 + g;
    const bool halfW = (cq < 2);

    // P1: t1a = relu(H @ eaW1h^T + biasA)
    ZACC(acc);
    GEMM_STAGED(acc, true, AH, 6, 8192, g_Iea1, 8192, 6, 64, cq*32);
    #pragma unroll
    for (int n = 0; n < 4; n++) {
        int col = cq*32 + n*8 + 2*t;
        float b0 = g_ea1b[rt*128 + col], b1 = g_ea1b[rt*128 + col + 1];
        float v0 = fmaxf(acc[n][0] + b0, 0.f), v1 = fmaxf(acc[n][1] + b1, 0.f);
        float v2 = fmaxf(acc[n][2] + b0, 0.f), v3 = fmaxf(acc[n][3] + b1, 0.f);
        int cu = col >> 1;
        int elA = rA*64 + (cu ^ sw), elB = rB*64 + (cu ^ sw);
        uint32 hi, lo;
        splitPack(v0, v1, hi, lo); AT1[elA] = hi; AT1[8192 + elA] = lo;
        splitPack(v2, v3, hi, lo); AT1[elB] = hi; AT1[8192 + elB] = lo;
    }

    // P2: a = t1a @ eaW2^T (raw, biases added in P4) — cq<2 warps only
    ZACC(accA);
    GEMM_STAGED(accA, halfW, AT1, 6, 8192, g_Iea2, 4096, 6, 64, cq*32);

    // P3: t1g
    ZACC(acc);
    GEMM_STAGED(acc, true, AH, 6, 8192, g_Ieg1, 8192, 6, 64, cq*32);
    #pragma unroll
    for (int n = 0; n < 4; n++) {
        int col = cq*32 + n*8 + 2*t;
        float b0 = g_eg1b[rt*128 + col], b1 = g_eg1b[rt*128 + col + 1];
        float v0 = fmaxf(acc[n][0] + b0, 0.f), v1 = fmaxf(acc[n][1] + b1, 0.f);
        float v2 = fmaxf(acc[n][2] + b0, 0.f), v3 = fmaxf(acc[n][3] + b1, 0.f);
        int cu = col >> 1;
        int elA = rA*64 + (cu ^ sw), elB = rB*64 + (cu ^ sw);
        uint32 hi, lo;
        splitPack(v0, v1, hi, lo); AT1[elA] = hi; AT1[8192 + elA] = lo;
        splitPack(v2, v3, hi, lo); AT1[elB] = hi; AT1[8192 + elB] = lo;
    }

    // P4: out = a - g  (eg2 image pre-negated) — cq<2 warps only
    ZACC(acc);
    GEMM_STAGED(acc, halfW, AT1, 6, 8192, g_Ieg2, 4096, 6, 64, cq*32);
    if (halfW) {
        #pragma unroll
        for (int n = 0; n < 4; n++) {
            int col = cq*32 + n*8 + 2*t;
            float e0 = eaB2[col] - egB2[col], e1 = eaB2[col+1] - egB2[col+1];
            float o0 = accA[n][0] + acc[n][0] + e0, o1 = accA[n][1] + acc[n][1] + e1;
            float o2 = accA[n][2] + acc[n][2] + e0, o3 = accA[n][3] + acc[n][3] + e1;
            int cu = col >> 1;
            int elA = rA*32 + (cu ^ sw), elB = rB*32 + (cu ^ sw);
            uint32 hi, lo;
            splitPack(o0, o1, hi, lo); AO[elA] = hi; AO[4096 + elA] = lo;
            splitPack(o2, o3, hi, lo); AO[elB] = hi; AO[4096 + elB] = lo;
        }
    }
    __syncthreads();

    // tension per row
    if (tid < 128) {
        int row = tid; float s = 0.f;
        int rsw = (row & 7) << 2;
        #pragma unroll 8
        for (int cu = 0; cu < 32; cu++) {
            int el = row*32 + (cu ^ rsw);
            float2 p = unpackBf(AO[el], AO[4096 + el]);
            s = fmaf(p.x, p.x, s); s = fmaf(p.y, p.y, s);
        }
        sTen[row] = s * (1.f/64.f);
    }
    __syncthreads();
    if (tid < 16) {
        float s = 0.f;
        #pragma unroll
        for (int b = 0; b < 8; b++) s += sTen[b*16 + tid];
        float avg = s * 0.125f;
        sAvg[tid] = avg; sExp[tid] = __expf(avg);
    }
    __syncthreads();
    if (tid < 64) {
        int cu = tid >> 1; float v = 0.f;
        for (int ci = 0; ci < 16; ci++) {
            float co = 0.f;
            #pragma unroll
            for (int b = 0; b < 8; b++) {
                int r = b*16 + ci;
                int el = r*32 + (cu ^ ((r & 7) << 2));
                float2 p = unpackBf(AO[el], AO[4096 + el]);
                co = fmaf(sAabs[b], (tid & 1) ? p.y : p.x, co);
            }
            v = fmaf(sExp[ci], co, v);
        }
        atomicAdd(&g_numer[tid], v);
    } else if (tid == 64) {
        float se = 0.f, st = 0.f;
        for (int ci = 0; ci < 16; ci++) { se += sExp[ci]; st += sAvg[ci]; }
        atomicAdd(&g_denom, se); atomicAdd(&g_tsum, st);
    }
    const float tenA = sTen[rA], tenB = sTen[rB];

    // gate r
    ZACC(acc);
    GEMM_STAGED(acc, true, AO, 5, 4096, g_Iwih[0], 4096, 5, 32, cq*32);
    GEMM_STAGED(acc, true, AH, 6, 8192, g_Iwhh[0], 8192, 6, 64, cq*32);
    #pragma unroll
    for (int n = 0; n < 4; n++) {
        int u = cq*32 + n*8 + 2*t;
        int pA = rA*128 + (u ^ sw), pB = rB*128 + (u ^ sw);
        sRN[pA]     = fsigm(acc[n][0] + bih[u] + bhh[u] + tenA*Wih[u*65 + 64]);
        sRN[pA + 1] = fsigm(acc[n][1] + bih[u+1] + bhh[u+1] + tenA*Wih[(u+1)*65 + 64]);
        sRN[pB]     = fsigm(acc[n][2] + bih[u] + bhh[u] + tenB*Wih[u*65 + 64]);
        sRN[pB + 1] = fsigm(acc[n][3] + bih[u+1] + bhh[u+1] + tenB*Wih[(u+1)*65 + 64]);
    }

    // gate n (inn from AO@wih2, hn from AH@whh2)
    ZACC(accA);
    GEMM_STAGED(accA, true, AO, 5, 4096, g_Iwih[2], 4096, 5, 32, cq*32);
    ZACC(acc);
    GEMM_STAGED(acc, true, AH, 6, 8192, g_Iwhh[2], 8192, 6, 64, cq*32);
    #pragma unroll
    for (int n = 0; n < 4; n++) {
        int u = cq*32 + n*8 + 2*t;
        int pA = rA*128 + (u ^ sw), pB = rB*128 + (u ^ sw);
        #pragma unroll
        for (int j = 0; j < 2; j++) {
            int uu = 256 + u + j;
            float rrA = sRN[pA + j];
            sRN[pA + j] = ftanh(accA[n][j] + bih[uu] + tenA*Wih[uu*65 + 64]
                                + rrA * (acc[n][j] + bhh[uu]));
            float rrB = sRN[pB + j];
            sRN[pB + j] = ftanh(accA[n][2+j] + bih[uu] + tenB*Wih[uu*65 + 64]
                                + rrB * (acc[n][2+j] + bhh[uu]));
        }
    }

    // gate z + combine -> newh (in place)
    ZACC(acc);
    GEMM_STAGED(acc, true, AO, 5, 4096, g_Iwih[1], 4096, 5, 32, cq*32);
    GEMM_STAGED(acc, true, AH, 6, 8192, g_Iwhh[1], 8192, 6, 64, cq*32);
    #pragma unroll
    for (int n = 0; n < 4; n++) {
        int u = cq*32 + n*8 + 2*t;
        int cu = u >> 1;
        int pA = rA*128 + (u ^ sw), pB = rB*128 + (u ^ sw);
        int eA = rA*64 + (cu ^ sw), eB = rB*64 + (cu ^ sw);
        float2 hA = unpackBf(AH[eA], AH[8192 + eA]);
        float2 hB = unpackBf(AH[eB], AH[8192 + eB]);
        #pragma unroll
        for (int j = 0; j < 2; j++) {
            int uu = 128 + u + j;
            float zA = fsigm(acc[n][j] + bih[uu] + bhh[uu] + tenA*Wih[uu*65 + 64]);
            float zB = fsigm(acc[n][2+j] + bih[uu] + bhh[uu] + tenB*Wih[uu*65 + 64]);
            float hAv = j ? hA.y : hA.x, hBv = j ? hB.y : hB.x;
            sRN[pA + j] = (1.f - zA)*sRN[pA + j] + zA*hAv;
            sRN[pB + j] = (1.f - zB)*sRN[pB + j] + zB*hBv;
        }
    }
    __syncthreads();

    // faction sums + copy-out
    const int f = c0 >> 11;
    const bool deb = (c0 & 2047) < 512;
    for (int idx = tid; idx < 1024; idx += 1024) {
        int b = idx >> 7, u = idx & 127;
        float s = 0.f;
        #pragma unroll
        for (int ci = 0; ci < 16; ci++)
            s += sRN[(b*16 + ci)*128 + (u ^ ((ci & 7) << 2))];
        atomicAdd(&g_fsum[(b*8 + f)*HIDD + u], s);
        if (deb) atomicAdd(&g_dsum[(b*8 + f)*HIDD + u], s);
    }
    for (int i = tid; i < 16384; i += 1024) {
        int r = i >> 7, k = i & 127;
        out[nh_off + ((long long)((r >> 4)*NCC + c0 + (r & 15)))*HIDD + k]
            = sRN[r*128 + (k ^ ((r & 7) << 2))];
    }
}

// ---------------- Stage C ----------------
__global__ void __launch_bounds__(1024) stageC(
    const float* __restrict__ mixW, const float* __restrict__ mixb,
    const float* __restrict__ headW, const float* __restrict__ headb,
    const int* __restrict__ stepp, float* __restrict__ out, long long nh_off)
{
    __shared__ float sMF[NB*HIDD];
    __shared__ float sC[OUTD];
    int tid = threadIdx.x;
    int lane = tid & 31, warp = tid >> 5;
    int st = *stepp;
    {
        int b = tid >> 7, u = tid & 127;
        float Sf = 0.f, Sd = 0.f;
        for (int f = 0; f < 8; f++) {
            float fsv = g_fsum[(b*8 + f)*HIDD + u];
            float fm = fsv * (1.f/2048.f);
            g_fm[(b*8 + f)*HIDD + u] = fm;
            Sf += fsv;
            Sd += 0.85f * g_dsum[(b*8 + f)*HIDD + u] + 76.8f * fm;
        }
        float m0 = Sf * (1.f/16384.f);
        g_m0[tid] = m0;
        sMF[tid] = (st > 5) ? (m0 + 0.15f * (0.25f*m0 - Sd * (1.f/16384.f))) : m0;
    }
    __syncthreads();
    // interf GEMV: warp per 4 outputs, lanes coalesced over k
    #pragma unroll
    for (int j2 = 0; j2 < 4; j2++) {
        int u = warp * 4 + j2;
        const float* wrow = mixW + u * 1024;
        float s = 0.f;
        #pragma unroll 8
        for (int i = lane; i < 1024; i += 32) s = fmaf(sMF[i], wrow[i], s);
        #pragma unroll
        for (int o = 16; o > 0; o >>= 1) s += __shfl_down_sync(0xFFFFFFFF, s, o);
        if (lane == 0) g_interf[u] = s + mixb[u];
    }
    if (tid >= 256 && tid < 320) sC[tid - 256] = g_numer[tid - 256] / g_denom;
    __syncthreads();
    if (tid < OUTD) {
        float p = headb[tid];
        #pragma unroll
        for (int o = 0; o < OUTD; o++) p = fmaf(sC[o], headW[tid*OUTD + o], p);
        out[tid] = p;
    } else if (tid == 64) {
        out[nh_off - 1] = g_tsum * (1.f/16384.f);
    }
}

// ---------------- Stage D (4 elems/thread) ----------------
__global__ void __launch_bounds__(256) stageD(const int* __restrict__ stepp,
                                              float* __restrict__ out, long long nh_off)
{
    long long base = ((long long)blockIdx.x*256 + threadIdx.x) * 4;
    int u = (int)(base & 127);
    long long rc = base >> 7;
    int c = (int)(rc & (NCC - 1));
    int b = (int)(rc >> 14);
    int f = c >> 11;
    bool dbg = (*stepp > 5) && ((c & 2047) < 512);
    float* p = out + nh_off + base;
    const float* fm = g_fm + (b*8 + f)*HIDD + u;
    const float* m0 = g_m0 + b*HIDD + u;
    const float* itf = g_interf + u;
    #pragma unroll
    for (int j = 0; j < 4; j++) {
        float v = 0.85f*p[j] + 0.15f*fm[j];
        if (dbg) v = 0.85f*v + 0.15f*m0[j];
        if (b == 0) v += 0.05f*itf[j];
        p[j] = v;
    }
}

extern "C" void kernel_launch(void* const* d_in, const int* in_sizes, int n_in,
                              void* d_out, int out_size) {
    const float* x     = (const float*)d_in[0];
    const float* noise = (const float*)d_in[1];
    const float* amps  = (const float*)d_in[2];
    const float* hidd  = (const float*)d_in[3];
    const float* eaW1  = (const float*)d_in[4];
    const float* eaB1  = (const float*)d_in[5];
    const float* eaW2  = (const float*)d_in[6];
    const float* eaB2  = (const float*)d_in[7];
    const float* egW1  = (const float*)d_in[8];
    const float* egB1  = (const float*)d_in[9];
    const float* egW2  = (const float*)d_in[10];
    const float* egB2  = (const float*)d_in[11];
    const float* Wih   = (const float*)d_in[12];
    const float* Whh   = (const float*)d_in[13];
    const float* bih   = (const float*)d_in[14];
    const float* bhh   = (const float*)d_in[15];
    const float* headW = (const float*)d_in[16];
    const float* headb = (const float*)d_in[17];
    const float* mixW  = (const float*)d_in[18];
    const float* mixb  = (const float*)d_in[19];
    const int*   step  = (const int*)d_in[20];
    float* out = (float*)d_out;
    long long nh_off = (long long)out_size - (long long)NB*NCC*HIDD;

    cudaFuncSetAttribute(stageB, cudaFuncAttributeMaxDynamicSharedMemorySize, SMEM_B_BYTES);

    stageA<<<1, 256>>>(x, noise, amps, eaW1, eaB1, egW1, egB1);
    stageA2<<<96, 256>>>(eaW1, egW1, eaW2, egW2, Wih, Whh);
    stageB<<<NCC/16, 1024, SMEM_B_BYTES>>>(hidd, Wih, bih, bhh, eaB2, egB2, out, nh_off);
    stageC<<<1, 1024>>>(mixW, mixb, headW, headb, step, out, nh_off);
    stageD<<<(NB*NCC*HIDD)/1024, 256>>>(step, out, nh_off);
}